// round 12
// baseline (speedup 1.0000x reference)
#include <cuda_runtime.h>
#include <cuda_fp16.h>
#include <cstdint>

// Problem dims
#define BB   32
#define LU   128
#define LC   512
#define SS   30
#define DD   768
#define HH   12
#define DK   64
#define DFF  1152

typedef __half  f16;
typedef __half2 f162;

// ---------------- fp32 scratch ----------------------------------------------
__device__ __align__(256) float g_fea_cur[BB*LU*DD];
__device__ __align__(256) float g_fea_ctx[BB*LC*DD];
__device__ __align__(256) float g_fea_slots[SS*BB*DD];
__device__ __align__(256) float g_cur_attn[BB*LU*DD];
__device__ __align__(256) float g_proj1[BB*SS*DD];
__device__ __align__(256) float g_va[SS*BB*DD];
__device__ __align__(256) float g_bkv0[2*DD];
__device__ __align__(256) float g_bkv1[2*DD];

// ---------------- f16 scratch (single precision everywhere) -----------------
__device__ __align__(256) f16 g_wn[3*DD*DD];
__device__ __align__(256) f16 g_wq[2*DD*DD];
__device__ __align__(256) f16 g_wkv0[DD*2*DD];
__device__ __align__(256) f16 g_wkv1[DD*2*DD];
__device__ __align__(256) f16 g_wo[2*DD*DD];
__device__ __align__(256) f16 g_w1[2*DD*DFF];
__device__ __align__(256) f16 g_w2[2*DFF*DD];
__device__ __align__(256) f16 g_xcur[BB*LU*DD];
__device__ __align__(256) f16 g_xctx[BB*LC*DD];
__device__ __align__(256) f16 g_xpre[SS*BB*DD];
__device__ __align__(256) f16 g_fc[BB*LU*DD];
__device__ __align__(256) f16 g_fx[BB*LC*DD];
__device__ __align__(256) f16 g_fs[SS*BB*DD];
__device__ __align__(256) f16 g_lnb[BB*LU*DD];
__device__ __align__(256) f16 g_ffh[BB*LU*DFF];
__device__ __align__(256) f16 g_a0[BB*LU*DD];
__device__ __align__(256) f16 g_a1[BB*SS*DD];
__device__ __align__(256) f16 g_co[BB*LU*DD];
__device__ __align__(256) f16 g_q0[BB*LU*DD];
__device__ __align__(256) f16 g_kv0[BB*LC*2*DD];
__device__ __align__(256) f16 g_q1[SS*BB*DD];
__device__ __align__(256) f16 g_kv1[BB*LU*2*DD];

// =================== helpers ================================================
__device__ __forceinline__ uint32_t smem_u32(const void* p) {
    uint32_t a;
    asm("{ .reg .u64 t; cvta.to.shared.u64 t, %1; cvt.u32.u64 %0, t; }" : "=r"(a) : "l"(p));
    return a;
}
__device__ __forceinline__ void ldm_x4(uint32_t* r, uint32_t addr) {
    asm volatile("ldmatrix.sync.aligned.m8n8.x4.shared.b16 {%0,%1,%2,%3}, [%4];"
                 : "=r"(r[0]), "=r"(r[1]), "=r"(r[2]), "=r"(r[3]) : "r"(addr));
}
__device__ __forceinline__ void ldm_x4_t(uint32_t* r, uint32_t addr) {
    asm volatile("ldmatrix.sync.aligned.m8n8.x4.trans.shared.b16 {%0,%1,%2,%3}, [%4];"
                 : "=r"(r[0]), "=r"(r[1]), "=r"(r[2]), "=r"(r[3]) : "r"(addr));
}
__device__ __forceinline__ void mma_f16(float* c, const uint32_t* a, const uint32_t* b) {
    asm volatile("mma.sync.aligned.m16n8k16.row.col.f32.f16.f16.f32 "
                 "{%0,%1,%2,%3}, {%4,%5,%6,%7}, {%8,%9}, {%0,%1,%2,%3};"
                 : "+f"(c[0]), "+f"(c[1]), "+f"(c[2]), "+f"(c[3])
                 : "r"(a[0]), "r"(a[1]), "r"(a[2]), "r"(a[3]), "r"(b[0]), "r"(b[1]));
}
__device__ __forceinline__ void mma_f16_b(float* c, const uint32_t* a, uint32_t b0, uint32_t b1) {
    asm volatile("mma.sync.aligned.m16n8k16.row.col.f32.f16.f16.f32 "
                 "{%0,%1,%2,%3}, {%4,%5,%6,%7}, {%8,%9}, {%0,%1,%2,%3};"
                 : "+f"(c[0]), "+f"(c[1]), "+f"(c[2]), "+f"(c[3])
                 : "r"(a[0]), "r"(a[1]), "r"(a[2]), "r"(a[3]), "r"(b0), "r"(b1));
}
__device__ __forceinline__ void split2h(float x, float y, f162& h, f162& l) {
    f16 hx = __float2half_rn(x), hy = __float2half_rn(y);
    h = __halves2half2(hx, hy);
    l = __halves2half2(__float2half_rn(x - __half2float(hx)),
                       __float2half_rn(y - __half2float(hy)));
}

// --------- merged fp32 -> f16 converter, with column packing ----------------
#define NSEG 12
struct ConvArgs {
    const float* x[NSEG];
    f16* h[NSEG];
    int n4[NSEG];
    int ldo4[NSEG];
    int coff4[NSEG];
};
__global__ __launch_bounds__(256)
void conv_multi(ConvArgs a)
{
    int s = blockIdx.y;
    int n4 = a.n4[s];
    const float* x = a.x[s];
    f16* h = a.h[s];
    int ldo4 = a.ldo4[s], coff4 = a.coff4[s];
    int stride = gridDim.x * 256;
    for (int i = blockIdx.x * 256 + threadIdx.x; i < n4; i += stride) {
        float4 v = ((const float4*)x)[i];
        f162 h01 = __halves2half2(__float2half_rn(v.x), __float2half_rn(v.y));
        f162 h23 = __halves2half2(__float2half_rn(v.z), __float2half_rn(v.w));
        int o4 = (i / 192) * ldo4 + coff4 + (i % 192);
        ((f162*)h)[2*o4]   = h01;
        ((f162*)h)[2*o4+1] = h23;
    }
}

// ===== single-f16 HMMA GEMM, KC=64 chunks, 2-stage cp.async =================
#define A_STRIDE 144           // 64 halves + 8 pad (conflict-free: 4r mod 32)
#define B_STRIDE 272
#define KC 64
#define B_TILE (64 * 272)      // 17408

template<int MT>
__device__ __forceinline__ void stage_load(
    uint32_t stg, const f16* __restrict__ A, const f16* __restrict__ B,
    int m0, int n0, int kc0, int M, int N, int K, int tid)
{
    constexpr int SA = MT * A_STRIDE;
    // A: MT rows x 64 halves = MT*8 16B segments
    #pragma unroll
    for (int i = 0; i < MT / 32; i++) {
        int ca = tid + (i << 8);
        int r = ca >> 3, seg = ca & 7;
        int m = m0 + r;
        uint32_t dst = stg + (uint32_t)(r * A_STRIDE + seg * 16);
        int sz = (m < M) ? 16 : 0;
        size_t so = (size_t)m * K + kc0 + seg * 8;
        asm volatile("cp.async.cg.shared.global [%0], [%1], 16, %2;"
                     :: "r"(dst), "l"(A + so), "r"(sz));
    }
    // B: 64 k-rows x 128 halves = 1024 16B segments
    #pragma unroll
    for (int i = 0; i < 4; i++) {
        int cb = tid + (i << 8);
        int r = cb >> 4, seg = cb & 15;
        uint32_t dst = stg + (uint32_t)(SA + r * B_STRIDE + seg * 16);
        size_t so = (size_t)(kc0 + r) * N + n0 + seg * 8;
        asm volatile("cp.async.cg.shared.global [%0], [%1], 16;"
                     :: "r"(dst), "l"(B + so));
    }
    asm volatile("cp.async.commit_group;");
}

template<int MT>
__global__ void __launch_bounds__(256, 3)
mma_gemm(const f16* __restrict__ A, const f16* __restrict__ B,
         float* __restrict__ C, int M, int N, int K,
         const float* __restrict__ bias, const float* __restrict__ res, int relu,
         f16* __restrict__ Ch)
{
    constexpr int SA  = MT * A_STRIDE;
    constexpr int TSTG = SA + B_TILE;
    constexpr int WM = (MT == 128) ? 4 : 2;
    constexpr int NP = (MT == 128) ? 4 : 2;

    extern __shared__ __align__(128) char smem[];
    const uint32_t sb = smem_u32(smem);
    const int tid = threadIdx.x;
    const int wid = tid >> 5, lane = tid & 31;
    const int m0 = blockIdx.y * MT, n0 = blockIdx.x * 128;
    const int mw = (wid % WM) * 32;
    const int nw = (wid / WM) * (NP * 16);

    float acc[2][NP * 2][4];
    #pragma unroll
    for (int i = 0; i < 2; i++)
        #pragma unroll
        for (int j = 0; j < NP * 2; j++)
            #pragma unroll
            for (int q = 0; q < 4; q++) acc[i][j][q] = 0.f;

    const int lsub = lane >> 3, lr = lane & 7;
    const uint32_t aOff = (uint32_t)((lr + (lsub & 1) * 8) * A_STRIDE + (lsub >> 1) * 16);
    const uint32_t bOff = (uint32_t)((lr + (lsub & 1) * 8) * B_STRIDE + (lsub >> 1) * 16);

    const int nc = K / KC;
    stage_load<MT>(sb, A, B, m0, n0, 0, M, N, K, tid);

    for (int c = 0; c < nc; c++) {
        if (c + 1 < nc) {
            stage_load<MT>(sb + ((c + 1) & 1) * TSTG, A, B,
                           m0, n0, (c + 1) * KC, M, N, K, tid);
            asm volatile("cp.async.wait_group 1;");
        } else {
            asm volatile("cp.async.wait_group 0;");
        }
        __syncthreads();

        const uint32_t st = sb + (c & 1) * TSTG;
        #pragma unroll
        for (int ks = 0; ks < KC; ks += 16) {
            uint32_t ah[2][4];
            #pragma unroll
            for (int mi = 0; mi < 2; mi++) {
                uint32_t off = aOff + (uint32_t)((mw + mi * 16) * A_STRIDE + ks * 2);
                ldm_x4(ah[mi], st + off);
            }
            #pragma unroll
            for (int np = 0; np < NP; np++) {
                uint32_t off = bOff + (uint32_t)(ks * B_STRIDE + (nw + np * 16) * 2);
                uint32_t bh[4];
                ldm_x4_t(bh, st + SA + off);
                #pragma unroll
                for (int mi = 0; mi < 2; mi++)
                    #pragma unroll
                    for (int g2 = 0; g2 < 2; g2++)
                        mma_f16(acc[mi][np * 2 + g2], ah[mi], bh + g2 * 2);
            }
        }
        __syncthreads();
    }

    // ---- epilogue
    const int qrow = lane >> 2, qcol = (lane & 3) * 2;
    #pragma unroll
    for (int mi = 0; mi < 2; mi++) {
        int r0 = m0 + mw + mi * 16 + qrow;
        #pragma unroll
        for (int ni = 0; ni < NP * 2; ni++) {
            int cidx = n0 + nw + ni * 8 + qcol;
            float* a = acc[mi][ni];
            #pragma unroll
            for (int hh = 0; hh < 2; hh++) {
                int r = r0 + hh * 8;
                if (r >= M) continue;
                float x = a[hh * 2 + 0] + bias[cidx];
                float y = a[hh * 2 + 1] + bias[cidx + 1];
                if (relu) { x = fmaxf(x, 0.f); y = fmaxf(y, 0.f); }
                if (res) {
                    const float2 rv = *(const float2*)&res[(size_t)r * N + cidx];
                    x += rv.x; y += rv.y;
                }
                if (C) {
                    float2 o; o.x = x; o.y = y;
                    *(float2*)&C[(size_t)r * N + cidx] = o;
                }
                if (Ch) {
                    *(f162*)&Ch[(size_t)r * N + cidx] =
                        __halves2half2(__float2half_rn(x), __float2half_rn(y));
                }
            }
        }
    }
}

#define STG128 (128 * A_STRIDE + B_TILE)
#define STG64  (64  * A_STRIDE + B_TILE)

// ====== fused flash attention (single Q/K/V, P split in regs for PV) ========
#define FA_STRIDE 144
#define FA_K 0
#define FA_V 18432
#define FA_MASK 36864
#define FA_SMEM (FA_MASK + 512)

__global__ void __launch_bounds__(256)
flash_attn(const f16* __restrict__ Q, const f16* __restrict__ K,
           const f16* __restrict__ V, const int* __restrict__ mask,
           f16* __restrict__ O,
           int Lq, int Lk, int qB, int qS, int oB, int kvld, float scale)
{
    extern __shared__ __align__(128) char smem[];
    const uint32_t sb = smem_u32(smem);
    const float* sbias = (const float*)(smem + FA_MASK);
    const int tid = threadIdx.x, wid = tid >> 5, lane = tid & 31;
    const int z = blockIdx.x, b = z / HH, h = z % HH;
    const int qt = lane >> 2, qc = (lane & 3) * 2;
    const int r0 = wid * 16 + qt, r1 = r0 + 8;
    const int colh = h * DK;

    uint32_t qf[4][4];
    #pragma unroll
    for (int ks = 0; ks < 4; ks++) {
        #pragma unroll
        for (int p = 0; p < 4; p++) {
            int rr = (p & 1) ? r1 : r0;
            int kk = ks * 16 + qc + ((p >> 1) ? 8 : 0);
            if (rr < Lq) {
                size_t off = (size_t)(b * qB + rr * qS) * DD + colh + kk;
                qf[ks][p] = *(const uint32_t*)(Q + off);
            } else qf[ks][p] = 0u;
        }
    }

    float m0 = -1e30f, m1 = -1e30f, l0 = 0.f, l1 = 0.f;
    float oacc[8][4];
    #pragma unroll
    for (int j = 0; j < 8; j++)
        #pragma unroll
        for (int q = 0; q < 4; q++) oacc[j][q] = 0.f;

    const uint32_t ldOffK = (uint32_t)(((lane & 7) + ((lane >> 3) & 1) * 8) * FA_STRIDE
                                       + ((lane >> 4) * 8) * 2);

    const int nch = Lk / 128;
    for (int ch = 0; ch < nch; ch++) {
        const int k0g = ch * 128;
        #pragma unroll
        for (int i = 0; i < 4; i++) {
            int idx = tid + (i << 8);
            int r = idx >> 3, seg = idx & 7;
            size_t src = (size_t)(b * Lk + k0g + r) * kvld + colh + seg * 8;
            uint32_t dst = sb + (uint32_t)(r * FA_STRIDE + seg * 16);
            asm volatile("cp.async.cg.shared.global [%0], [%1], 16;" :: "r"(dst + FA_K), "l"(K + src));
            asm volatile("cp.async.cg.shared.global [%0], [%1], 16;" :: "r"(dst + FA_V), "l"(V + src));
        }
        asm volatile("cp.async.commit_group;");
        if (tid < 128)
            ((float*)(smem + FA_MASK))[tid] = mask[b * Lk + k0g + tid] ? 0.f : -1e9f;
        asm volatile("cp.async.wait_group 0;");
        __syncthreads();

        float sacc[16][4];
        #pragma unroll
        for (int j = 0; j < 16; j++)
            #pragma unroll
            for (int q = 0; q < 4; q++) sacc[j][q] = 0.f;

        #pragma unroll
        for (int ks = 0; ks < 4; ks++) {
            #pragma unroll
            for (int nt = 0; nt < 8; nt++) {
                uint32_t off = ldOffK + (uint32_t)(nt * 16 * FA_STRIDE + ks * 32);
                uint32_t kh4[4];
                ldm_x4(kh4, sb + FA_K + off);
                #pragma unroll
                for (int sub = 0; sub < 2; sub++)
                    mma_f16_b(sacc[nt * 2 + sub], qf[ks], kh4[sub], kh4[sub + 2]);
            }
        }

        float cm0 = -1e30f, cm1 = -1e30f;
        #pragma unroll
        for (int j = 0; j < 16; j++) {
            int kb = j * 8 + qc;
            float b0v = sbias[kb], b1v = sbias[kb + 1];
            sacc[j][0] = sacc[j][0] * scale + b0v;
            sacc[j][1] = sacc[j][1] * scale + b1v;
            sacc[j][2] = sacc[j][2] * scale + b0v;
            sacc[j][3] = sacc[j][3] * scale + b1v;
            cm0 = fmaxf(cm0, fmaxf(sacc[j][0], sacc[j][1]));
            cm1 = fmaxf(cm1, fmaxf(sacc[j][2], sacc[j][3]));
        }
        cm0 = fmaxf(cm0, __shfl_xor_sync(0xFFFFFFFFu, cm0, 1));
        cm0 = fmaxf(cm0, __shfl_xor_sync(0xFFFFFFFFu, cm0, 2));
        cm1 = fmaxf(cm1, __shfl_xor_sync(0xFFFFFFFFu, cm1, 1));
        cm1 = fmaxf(cm1, __shfl_xor_sync(0xFFFFFFFFu, cm1, 2));
        float nm0 = fmaxf(m0, cm0), nm1 = fmaxf(m1, cm1);
        float al0 = __expf(m0 - nm0), al1 = __expf(m1 - nm1);
        m0 = nm0; m1 = nm1;

        float ps0 = 0.f, ps1 = 0.f;
        #pragma unroll
        for (int j = 0; j < 16; j++) {
            float p0 = __expf(sacc[j][0] - nm0), p1 = __expf(sacc[j][1] - nm0);
            float p2 = __expf(sacc[j][2] - nm1), p3 = __expf(sacc[j][3] - nm1);
            ps0 += p0 + p1; ps1 += p2 + p3;
            sacc[j][0] = p0; sacc[j][1] = p1; sacc[j][2] = p2; sacc[j][3] = p3;
        }
        ps0 += __shfl_xor_sync(0xFFFFFFFFu, ps0, 1);
        ps0 += __shfl_xor_sync(0xFFFFFFFFu, ps0, 2);
        ps1 += __shfl_xor_sync(0xFFFFFFFFu, ps1, 1);
        ps1 += __shfl_xor_sync(0xFFFFFFFFu, ps1, 2);
        l0 = l0 * al0 + ps0; l1 = l1 * al1 + ps1;
        #pragma unroll
        for (int j = 0; j < 8; j++) {
            oacc[j][0] *= al0; oacc[j][1] *= al0;
            oacc[j][2] *= al1; oacc[j][3] *= al1;
        }

        #pragma unroll
        for (int kk = 0; kk < 8; kk++) {
            uint32_t ahp[4], alp[4];
            #pragma unroll
            for (int jj = 0; jj < 2; jj++) {
                const float* sp = sacc[2 * kk + jj];
                f162 h01, l01, h23, l23;
                split2h(sp[0], sp[1], h01, l01);
                split2h(sp[2], sp[3], h23, l23);
                ahp[jj * 2 + 0] = *(uint32_t*)&h01; ahp[jj * 2 + 1] = *(uint32_t*)&h23;
                alp[jj * 2 + 0] = *(uint32_t*)&l01; alp[jj * 2 + 1] = *(uint32_t*)&l23;
            }
            #pragma unroll
            for (int dt = 0; dt < 4; dt++) {
                uint32_t off = ldOffK + (uint32_t)(kk * 16 * FA_STRIDE + dt * 32);
                uint32_t vh4[4];
                ldm_x4_t(vh4, sb + FA_V + off);
                #pragma unroll
                for (int sub = 0; sub < 2; sub++)
                    mma_f16_b(oacc[dt * 2 + sub], ahp, vh4[sub*2], vh4[sub*2+1]);
                #pragma unroll
                for (int sub = 0; sub < 2; sub++)
                    mma_f16_b(oacc[dt * 2 + sub], alp, vh4[sub*2], vh4[sub*2+1]);
            }
        }
        __syncthreads();
    }

    float inv0 = 1.f / l0, inv1 = 1.f / l1;
    #pragma unroll
    for (int j = 0; j < 8; j++) {
        int col = colh + j * 8 + qc;
        if (r0 < Lq) {
            size_t off = (size_t)(b * oB + r0) * DD + col;
            *(f162*)(O + off) = __halves2half2(__float2half_rn(oacc[j][0] * inv0),
                                               __float2half_rn(oacc[j][1] * inv0));
        }
        if (r1 < Lq) {
            size_t off = (size_t)(b * oB + r1) * DD + col;
            *(f162*)(O + off) = __halves2half2(__float2half_rn(oacc[j][2] * inv1),
                                               __float2half_rn(oacc[j][3] * inv1));
        }
    }
}

// ------- LayerNorm: warp per row, single pass, register resident ------------
__global__ __launch_bounds__(256)
void ln_warp(const float* __restrict__ x, float* __restrict__ y,
             f16* __restrict__ yh,
             const float* __restrict__ g, const float* __restrict__ be)
{
    const int lane = threadIdx.x & 31;
    const size_t row = (size_t)(blockIdx.x * 8) + (threadIdx.x >> 5);
    const float* xr = x + row * DD;

    float4 v[6];
    float s = 0.f, s2 = 0.f;
    #pragma unroll
    for (int i = 0; i < 6; i++) {
        v[i] = *(const float4*)&xr[i * 128 + lane * 4];
        s  += v[i].x + v[i].y + v[i].z + v[i].w;
        s2 += v[i].x * v[i].x + v[i].y * v[i].y + v[i].z * v[i].z + v[i].w * v[i].w;
    }
    #pragma unroll
    for (int o = 16; o > 0; o >>= 1) {
        s  += __shfl_xor_sync(0xFFFFFFFFu, s, o);
        s2 += __shfl_xor_sync(0xFFFFFFFFu, s2, o);
    }
    const float mean = s * (1.f / DD);
    const float var  = s2 * (1.f / DD) - mean * mean;
    const float rstd = rsqrtf(var + 1e-5f);

    #pragma unroll
    for (int i = 0; i < 6; i++) {
        int col = i * 128 + lane * 4;
        float4 gv = *(const float4*)&g[col];
        float4 bv = *(const float4*)&be[col];
        float4 o;
        o.x = (v[i].x - mean) * rstd * gv.x + bv.x;
        o.y = (v[i].y - mean) * rstd * gv.y + bv.y;
        o.z = (v[i].z - mean) * rstd * gv.z + bv.z;
        o.w = (v[i].w - mean) * rstd * gv.w + bv.w;
        if (y) *(float4*)&y[row * DD + col] = o;
        if (yh) {
            *(f162*)&yh[row * DD + col] =
                __halves2half2(__float2half_rn(o.x), __float2half_rn(o.y));
            *(f162*)&yh[row * DD + col + 2] =
                __halves2half2(__float2half_rn(o.z), __float2half_rn(o.w));
        }
    }
}

// ---------------- va = fea_slots[S,B,D] + proj1[B,S,D] transposed -----------
__global__ __launch_bounds__(256)
void va_kernel(const float* __restrict__ slots, const float* __restrict__ proj,
               float* __restrict__ va)
{
    int idx = blockIdx.x * 256 + threadIdx.x;
    if (idx >= SS * BB * DD) return;
    int d = idx % DD;
    int r = idx / DD;
    int s = r / BB, b = r % BB;
    va[idx] = slots[idx] + proj[((long long)b * SS + s) * DD + d];
}

// ---------------- host-side helpers ----------------------------------------
template<typename T>
static T* sym(const void* s) { void* p = nullptr; cudaGetSymbolAddress(&p, s); return (T*)p; }

static void run_lin_s(cudaStream_t st, const f16* A, const f16* W,
                      float* C, int M, int N, int K,
                      const float* bias, const float* res, int relu,
                      f16* Ch = nullptr)
{
    int ctas128 = (N / 128) * ((M + 127) / 128);
    if (M <= 4096 && ctas128 < 232) {
        dim3 grid(N / 128, (M + 63) / 64);
        mma_gemm<64><<<grid, 256, 2 * STG64, st>>>(A, W, C, M, N, K, bias, res, relu, Ch);
    } else {
        dim3 grid(N / 128, (M + 127) / 128);
        mma_gemm<128><<<grid, 256, 2 * STG128, st>>>(A, W, C, M, N, K, bias, res, relu, Ch);
    }
}

extern "C" void kernel_launch(void* const* d_in, const int* in_sizes, int n_in,
                              void* d_out, int out_size)
{
    static bool s_init = false;
    static cudaStream_t s1, s2;
    static cudaEvent_t e0, e1, e2;
    if (!s_init) {
        cudaFuncSetAttribute(mma_gemm<128>, cudaFuncAttributeMaxDynamicSharedMemorySize, 2 * STG128);
        cudaFuncSetAttribute(mma_gemm<64>,  cudaFuncAttributeMaxDynamicSharedMemorySize, 2 * STG64);
        cudaFuncSetAttribute(flash_attn, cudaFuncAttributeMaxDynamicSharedMemorySize, FA_SMEM);
        cudaStreamCreateWithFlags(&s1, cudaStreamNonBlocking);
        cudaStreamCreateWithFlags(&s2, cudaStreamNonBlocking);
        cudaEventCreateWithFlags(&e0, cudaEventDisableTiming);
        cudaEventCreateWithFlags(&e1, cudaEventDisableTiming);
        cudaEventCreateWithFlags(&e2, cudaEventDisableTiming);
        s_init = true;
    }

    const float* cur_raw  = (const float*)d_in[0];
    const float* ctx_raw  = (const float*)d_in[1];
    const float* pre_raw  = (const float*)d_in[2];
    const int*   ctx_mask = (const int*)d_in[3];
    const int*   utt_mask = (const int*)d_in[4];
    const float* norm_W   = (const float*)d_in[5];
    const float* norm_b   = (const float*)d_in[6];
    const float* norm_g   = (const float*)d_in[7];
    const float* norm_be  = (const float*)d_in[8];
    const float* Wq = (const float*)d_in[9];
    const float* bq = (const float*)d_in[10];
    const float* Wk = (const float*)d_in[11];
    const float* bk = (const float*)d_in[12];
    const float* Wv = (const float*)d_in[13];
    const float* bv = (const float*)d_in[14];
    const float* Wo = (const float*)d_in[15];
    const float* bo = (const float*)d_in[16];
    const float* ln_g = (const float*)d_in[17];
    const float* ln_b = (const float*)d_in[18];
    const float* W1 = (const float*)d_in[19];
    const float* b1 = (const float*)d_in[20];
    const float* W2 = (const float*)d_in[21];
    const float* b2 = (const float*)d_in[22];

    float* out  = (float*)d_out;
    float* cur_out   = out;
    float* slots_out = out + (long long)BB * LU * DD;

    float* fea_cur   = sym<float>(g_fea_cur);
    float* fea_ctx   = sym<float>(g_fea_ctx);
    float* fea_slots = sym<float>(g_fea_slots);
    float* cur_attn  = sym<float>(g_cur_attn);
    float* proj1 = sym<float>(g_proj1);
    float* va = sym<float>(g_va);
    float* bkv0 = sym<float>(g_bkv0);
    float* bkv1 = sym<float>(g_bkv1);

    f16 *wn = sym<f16>(g_wn);
    f16 *wq = sym<f16>(g_wq);
    f16 *wkv0 = sym<f16>(g_wkv0);
    f16 *wkv1 = sym<f16>(g_wkv1);
    f16 *wo = sym<f16>(g_wo);
    f16 *w1 = sym<f16>(g_w1);
    f16 *w2 = sym<f16>(g_w2);
    f16 *xcur = sym<f16>(g_xcur);
    f16 *xctx = sym<f16>(g_xctx);
    f16 *xpre = sym<f16>(g_xpre);
    f16 *fc = sym<f16>(g_fc);
    f16 *fx = sym<f16>(g_fx);
    f16 *fs = sym<f16>(g_fs);
    f16 *lnb = sym<f16>(g_lnb);
    f16 *ffh = sym<f16>(g_ffh);
    f16 *a0 = sym<f16>(g_a0);
    f16 *a1 = sym<f16>(g_a1);
    f16 *co = sym<f16>(g_co);
    f16 *q0 = sym<f16>(g_q0);
    f16 *kv0 = sym<f16>(g_kv0);
    f16 *q1 = sym<f16>(g_q1);
    f16 *kv1 = sym<f16>(g_kv1);

    const int DxD = DD * DD;
    const int N2 = 2 * DD;

    // ---- packed biases
    cudaMemcpyAsync(bkv0,      bk,      DD * 4, cudaMemcpyDeviceToDevice, 0);
    cudaMemcpyAsync(bkv0 + DD, bv,      DD * 4, cudaMemcpyDeviceToDevice, 0);
    cudaMemcpyAsync(bkv1,      bk + DD, DD * 4, cudaMemcpyDeviceToDevice, 0);
    cudaMemcpyAsync(bkv1 + DD, bv + DD, DD * 4, cudaMemcpyDeviceToDevice, 0);

    // ---- one launch for ALL fp32->f16 conversions (with KV weight packing)
    {
        ConvArgs ca;
        const float* xs[NSEG] = { norm_W, Wq, Wo, W1, W2,
                                  Wk, Wv, Wk + DxD, Wv + DxD,
                                  cur_raw, ctx_raw, pre_raw };
        f16* hs[NSEG] = { wn, wq, wo, w1, w2,
                          wkv0, wkv0, wkv1, wkv1,
                          xcur, xctx, xpre };
        int ns[NSEG] = { 3*DxD/4, 2*DxD/4, 2*DxD/4, 2*DD*DFF/4, 2*DFF*DD/4,
                         DxD/4, DxD/4, DxD/4, DxD/4,
                         BB*LU*DD/4, BB*LC*DD/4, SS*BB*DD/4 };
        int ld4[NSEG] = { 192, 192, 192, 192, 192, 384, 384, 384, 384, 192, 192, 192 };
        int co4[NSEG] = { 0, 0, 0, 0, 0, 0, 192, 0, 192, 0, 0, 0 };
        for (int i = 0; i < NSEG; i++) {
            ca.x[i]=xs[i]; ca.h[i]=hs[i];
            ca.n4[i]=ns[i]; ca.ldo4[i]=ld4[i]; ca.coff4[i]=co4[i];
        }
        conv_multi<<<dim3(128, NSEG), 256>>>(ca);
    }
    cudaEventRecord(e0, 0);
    cudaStreamWaitEvent(s1, e0, 0);
    cudaStreamWaitEvent(s2, e0, 0);

    // ---- s1: cur chain (norm -> LN -> Q0)
    run_lin_s(s1, xcur, wn, fea_cur, BB * LU, DD, DD, norm_b, nullptr, 0);
    ln_warp<<<BB * LU / 8, 256, 0, s1>>>(fea_cur, fea_cur, fc, norm_g, norm_be);
    run_lin_s(s1, fc, wq, nullptr, BB * LU, DD, DD, bq, nullptr, 0, q0);
    cudaEventRecord(e1, s1);

    // ---- s2: slots chain (norm -> LN -> Q1)
    run_lin_s(s2, xpre, wn + 2 * DxD, fea_slots, SS * BB, DD, DD,
              norm_b + 2 * DD, nullptr, 0);
    ln_warp<<<SS * BB / 8, 256, 0, s2>>>(fea_slots, fea_slots, fs,
                                         norm_g + 2 * DD, norm_be + 2 * DD);
    run_lin_s(s2, fs, wq + DxD, nullptr, SS * BB, DD, DD, bq + DD, nullptr, 0, q1);
    cudaEventRecord(e2, s2);

    // ---- main: ctx chain (norm -> LN -> fused K0|V0)
    run_lin_s(0, xctx, wn + DxD, fea_ctx, BB * LC, DD, DD, norm_b + DD, nullptr, 0);
    ln_warp<<<BB * LC / 8, 256>>>(fea_ctx, nullptr, fx, norm_g + DD, norm_be + DD);
    run_lin_s(0, fx, wkv0, nullptr, BB * LC, N2, DD, bkv0, nullptr, 0, kv0);

    cudaStreamWaitEvent(0, e1, 0);

    // ---- stage B (main)
    flash_attn<<<BB * HH, 256, FA_SMEM>>>(q0, kv0, kv0 + DD, ctx_mask, a0,
                                          LU, LC, LU, 1, LU, N2, 0.125f);
    run_lin_s(0, a0, wo, cur_attn, BB * LU, DD, DD, bo, fea_cur, 0);
    ln_warp<<<BB * LU / 8, 256>>>(cur_attn, nullptr, lnb, ln_g, ln_b);
    run_lin_s(0, lnb, w1, nullptr, BB * LU, DFF, DD, b1, nullptr, 1, ffh);
    run_lin_s(0, ffh, w2, cur_out, BB * LU, DD, DFF, b2, cur_attn, 0, co);

    // ---- stage C (main): fused K1|V1
    run_lin_s(0, co, wkv1, nullptr, BB * LU, N2, DD, bkv1, nullptr, 0, kv1);

    cudaStreamWaitEvent(0, e2, 0);

    flash_attn<<<BB * HH, 256, FA_SMEM>>>(q1, kv1, kv1 + DD, utt_mask, a1,
                                          SS, LU, 1, BB, SS, N2, 0.125f);

    run_lin_s(0, a1, wo + DxD, proj1, BB * SS, DD, DD, bo + DD, nullptr, 0);
    va_kernel<<<(SS * BB * DD + 255) / 256, 256>>>(fea_slots, proj1, va);

    ln_warp<<<SS * BB / 8, 256>>>(va, nullptr, lnb, ln_g + DD, ln_b + DD);
    run_lin_s(0, lnb, w1 + DD * DFF, nullptr, SS * BB, DFF, DD, b1 + DFF, nullptr, 1, ffh);
    run_lin_s(0, ffh, w2 + DFF * DD, slots_out, SS * BB, DD, DFF, b2 + DD, va, 0);
}

// round 13
// speedup vs baseline: 1.3616x; 1.3616x over previous
#include <cuda_runtime.h>
#include <cuda_fp16.h>
#include <cstdint>

// Problem dims
#define BB   32
#define LU   128
#define LC   512
#define SS   30
#define DD   768
#define HH   12
#define DK   64
#define DFF  1152

typedef __half  f16;
typedef __half2 f162;

// ---------------- fp32 scratch ----------------------------------------------
__device__ __align__(256) float g_fea_cur[BB*LU*DD];
__device__ __align__(256) float g_fea_ctx[BB*LC*DD];
__device__ __align__(256) float g_fea_slots[SS*BB*DD];
__device__ __align__(256) float g_cur_attn[BB*LU*DD];
__device__ __align__(256) float g_proj1[BB*SS*DD];
__device__ __align__(256) float g_va[SS*BB*DD];
__device__ __align__(256) float g_bkv0[2*DD];
__device__ __align__(256) float g_bkv1[2*DD];

// ---------------- f16 scratch (single precision everywhere) -----------------
__device__ __align__(256) f16 g_wn[3*DD*DD];
__device__ __align__(256) f16 g_wq[2*DD*DD];
__device__ __align__(256) f16 g_wkv0[DD*2*DD];
__device__ __align__(256) f16 g_wkv1[DD*2*DD];
__device__ __align__(256) f16 g_wo[2*DD*DD];
__device__ __align__(256) f16 g_w1[2*DD*DFF];
__device__ __align__(256) f16 g_w2[2*DFF*DD];
__device__ __align__(256) f16 g_xcur[BB*LU*DD];
__device__ __align__(256) f16 g_xctx[BB*LC*DD];
__device__ __align__(256) f16 g_xpre[SS*BB*DD];
__device__ __align__(256) f16 g_fc[BB*LU*DD];
__device__ __align__(256) f16 g_fx[BB*LC*DD];
__device__ __align__(256) f16 g_fs[SS*BB*DD];
__device__ __align__(256) f16 g_lnb[BB*LU*DD];
__device__ __align__(256) f16 g_ffh[BB*LU*DFF];
__device__ __align__(256) f16 g_a0[BB*LU*DD];
__device__ __align__(256) f16 g_a1[BB*SS*DD];
__device__ __align__(256) f16 g_co[BB*LU*DD];
__device__ __align__(256) f16 g_q0[BB*LU*DD];
__device__ __align__(256) f16 g_kv0[BB*LC*2*DD];
__device__ __align__(256) f16 g_q1[SS*BB*DD];
__device__ __align__(256) f16 g_kv1[BB*LU*2*DD];

// =================== helpers ================================================
__device__ __forceinline__ uint32_t smem_u32(const void* p) {
    uint32_t a;
    asm("{ .reg .u64 t; cvta.to.shared.u64 t, %1; cvt.u32.u64 %0, t; }" : "=r"(a) : "l"(p));
    return a;
}
__device__ __forceinline__ void ldm_x4(uint32_t* r, uint32_t addr) {
    asm volatile("ldmatrix.sync.aligned.m8n8.x4.shared.b16 {%0,%1,%2,%3}, [%4];"
                 : "=r"(r[0]), "=r"(r[1]), "=r"(r[2]), "=r"(r[3]) : "r"(addr));
}
__device__ __forceinline__ void ldm_x4_t(uint32_t* r, uint32_t addr) {
    asm volatile("ldmatrix.sync.aligned.m8n8.x4.trans.shared.b16 {%0,%1,%2,%3}, [%4];"
                 : "=r"(r[0]), "=r"(r[1]), "=r"(r[2]), "=r"(r[3]) : "r"(addr));
}
__device__ __forceinline__ void mma_f16(float* c, const uint32_t* a, const uint32_t* b) {
    asm volatile("mma.sync.aligned.m16n8k16.row.col.f32.f16.f16.f32 "
                 "{%0,%1,%2,%3}, {%4,%5,%6,%7}, {%8,%9}, {%0,%1,%2,%3};"
                 : "+f"(c[0]), "+f"(c[1]), "+f"(c[2]), "+f"(c[3])
                 : "r"(a[0]), "r"(a[1]), "r"(a[2]), "r"(a[3]), "r"(b[0]), "r"(b[1]));
}
__device__ __forceinline__ void mma_f16_b(float* c, const uint32_t* a, uint32_t b0, uint32_t b1) {
    asm volatile("mma.sync.aligned.m16n8k16.row.col.f32.f16.f16.f32 "
                 "{%0,%1,%2,%3}, {%4,%5,%6,%7}, {%8,%9}, {%0,%1,%2,%3};"
                 : "+f"(c[0]), "+f"(c[1]), "+f"(c[2]), "+f"(c[3])
                 : "r"(a[0]), "r"(a[1]), "r"(a[2]), "r"(a[3]), "r"(b0), "r"(b1));
}
__device__ __forceinline__ void split2h(float x, float y, f162& h, f162& l) {
    f16 hx = __float2half_rn(x), hy = __float2half_rn(y);
    h = __halves2half2(hx, hy);
    l = __halves2half2(__float2half_rn(x - __half2float(hx)),
                       __float2half_rn(y - __half2float(hy)));
}

// --------- merged fp32 -> f16 converter, with column packing ----------------
#define NSEG 12
struct ConvArgs {
    const float* x[NSEG];
    f16* h[NSEG];
    int n4[NSEG];
    int ldo4[NSEG];
    int coff4[NSEG];
};
__global__ __launch_bounds__(256)
void conv_multi(ConvArgs a)
{
    int s = blockIdx.y;
    int n4 = a.n4[s];
    const float* x = a.x[s];
    f16* h = a.h[s];
    int ldo4 = a.ldo4[s], coff4 = a.coff4[s];
    int stride = gridDim.x * 256;
    for (int i = blockIdx.x * 256 + threadIdx.x; i < n4; i += stride) {
        float4 v = ((const float4*)x)[i];
        f162 h01 = __halves2half2(__float2half_rn(v.x), __float2half_rn(v.y));
        f162 h23 = __halves2half2(__float2half_rn(v.z), __float2half_rn(v.w));
        int o4 = (i / 192) * ldo4 + coff4 + (i % 192);
        ((f162*)h)[2*o4]   = h01;
        ((f162*)h)[2*o4+1] = h23;
    }
}

// ========= single-f16 HMMA GEMM, KC=32, 2-stage cp.async ====================
#define A_STRIDE 80
#define B_STRIDE 272
#define KC 32
#define B_TILE 8704            // 32 * 272

template<int MT>
__device__ __forceinline__ void stage_load(
    uint32_t stg, const f16* __restrict__ A, const f16* __restrict__ B,
    int m0, int n0, int kc0, int M, int N, int K, int tid)
{
    constexpr int SA = MT * A_STRIDE;
    #pragma unroll
    for (int i = 0; i < MT / 64; i++) {
        int ca = tid + (i << 8);
        int r = ca >> 2, seg = ca & 3;
        int m = m0 + r;
        uint32_t dst = stg + (uint32_t)(r * A_STRIDE + seg * 16);
        int sz = (m < M) ? 16 : 0;
        size_t so = (size_t)m * K + kc0 + seg * 8;
        asm volatile("cp.async.cg.shared.global [%0], [%1], 16, %2;"
                     :: "r"(dst), "l"(A + so), "r"(sz));
    }
    #pragma unroll
    for (int i = 0; i < 2; i++) {
        int cb = tid + (i << 8);
        int r = cb >> 4, seg = cb & 15;
        uint32_t dst = stg + (uint32_t)(SA + r * B_STRIDE + seg * 16);
        size_t so = (size_t)(kc0 + r) * N + n0 + seg * 8;
        asm volatile("cp.async.cg.shared.global [%0], [%1], 16;"
                     :: "r"(dst), "l"(B + so));
    }
    asm volatile("cp.async.commit_group;");
}

template<int MT>
__global__ void __launch_bounds__(256, 3)
mma_gemm(const f16* __restrict__ A, const f16* __restrict__ B,
         float* __restrict__ C, int M, int N, int K,
         const float* __restrict__ bias, const float* __restrict__ res, int relu,
         f16* __restrict__ Ch)
{
    constexpr int SA  = MT * A_STRIDE;
    constexpr int TSTG = SA + B_TILE;
    constexpr int WM = (MT == 128) ? 4 : 2;
    constexpr int NP = (MT == 128) ? 4 : 2;

    extern __shared__ __align__(128) char smem[];
    const uint32_t sb = smem_u32(smem);
    const int tid = threadIdx.x;
    const int wid = tid >> 5, lane = tid & 31;
    const int m0 = blockIdx.y * MT, n0 = blockIdx.x * 128;
    const int mw = (wid % WM) * 32;
    const int nw = (wid / WM) * (NP * 16);

    float acc[2][NP * 2][4];
    #pragma unroll
    for (int i = 0; i < 2; i++)
        #pragma unroll
        for (int j = 0; j < NP * 2; j++)
            #pragma unroll
            for (int q = 0; q < 4; q++) acc[i][j][q] = 0.f;

    const int lsub = lane >> 3, lr = lane & 7;
    const uint32_t aOff = (uint32_t)((lr + (lsub & 1) * 8) * A_STRIDE + (lsub >> 1) * 16);
    const uint32_t bOff = (uint32_t)((lr + (lsub & 1) * 8) * B_STRIDE + (lsub >> 1) * 16);

    const int nc = K / KC;
    stage_load<MT>(sb, A, B, m0, n0, 0, M, N, K, tid);

    for (int c = 0; c < nc; c++) {
        if (c + 1 < nc) {
            stage_load<MT>(sb + ((c + 1) & 1) * TSTG, A, B,
                           m0, n0, (c + 1) * KC, M, N, K, tid);
            asm volatile("cp.async.wait_group 1;");
        } else {
            asm volatile("cp.async.wait_group 0;");
        }
        __syncthreads();

        const uint32_t st = sb + (c & 1) * TSTG;
        #pragma unroll
        for (int ks = 0; ks < KC; ks += 16) {
            // batch ALL ldmatrix issues for this ks-step first (long load run),
            // then the full MMA block — no load->mma adjacency
            uint32_t ah[2][4], bh[NP][4];
            #pragma unroll
            for (int mi = 0; mi < 2; mi++) {
                uint32_t off = aOff + (uint32_t)((mw + mi * 16) * A_STRIDE + ks * 2);
                ldm_x4(ah[mi], st + off);
            }
            #pragma unroll
            for (int np = 0; np < NP; np++) {
                uint32_t off = bOff + (uint32_t)(ks * B_STRIDE + (nw + np * 16) * 2);
                ldm_x4_t(bh[np], st + SA + off);
            }
            #pragma unroll
            for (int np = 0; np < NP; np++)
                #pragma unroll
                for (int mi = 0; mi < 2; mi++)
                    #pragma unroll
                    for (int g2 = 0; g2 < 2; g2++)
                        mma_f16(acc[mi][np * 2 + g2], ah[mi], bh[np] + g2 * 2);
        }
        __syncthreads();
    }

    // ---- epilogue
    const int qrow = lane >> 2, qcol = (lane & 3) * 2;
    #pragma unroll
    for (int mi = 0; mi < 2; mi++) {
        int r0 = m0 + mw + mi * 16 + qrow;
        #pragma unroll
        for (int ni = 0; ni < NP * 2; ni++) {
            int cidx = n0 + nw + ni * 8 + qcol;
            float* a = acc[mi][ni];
            #pragma unroll
            for (int hh = 0; hh < 2; hh++) {
                int r = r0 + hh * 8;
                if (r >= M) continue;
                float x = a[hh * 2 + 0] + bias[cidx];
                float y = a[hh * 2 + 1] + bias[cidx + 1];
                if (relu) { x = fmaxf(x, 0.f); y = fmaxf(y, 0.f); }
                if (res) {
                    const float2 rv = *(const float2*)&res[(size_t)r * N + cidx];
                    x += rv.x; y += rv.y;
                }
                if (C) {
                    float2 o; o.x = x; o.y = y;
                    *(float2*)&C[(size_t)r * N + cidx] = o;
                }
                if (Ch) {
                    *(f162*)&Ch[(size_t)r * N + cidx] =
                        __halves2half2(__float2half_rn(x), __float2half_rn(y));
                }
            }
        }
    }
}

#define STG128 (128 * A_STRIDE + B_TILE)
#define STG64  (64  * A_STRIDE + B_TILE)

// ====== fused flash attention (single Q/K/V, P split in regs for PV) ========
#define FA_STRIDE 144
#define FA_K 0
#define FA_V 18432
#define FA_MASK 36864
#define FA_SMEM (FA_MASK + 512)

__global__ void __launch_bounds__(256)
flash_attn(const f16* __restrict__ Q, const f16* __restrict__ K,
           const f16* __restrict__ V, const int* __restrict__ mask,
           f16* __restrict__ O,
           int Lq, int Lk, int qB, int qS, int oB, int kvld, float scale)
{
    extern __shared__ __align__(128) char smem[];
    const uint32_t sb = smem_u32(smem);
    const float* sbias = (const float*)(smem + FA_MASK);
    const int tid = threadIdx.x, wid = tid >> 5, lane = tid & 31;
    const int z = blockIdx.x, b = z / HH, h = z % HH;
    const int qt = lane >> 2, qc = (lane & 3) * 2;
    const int r0 = wid * 16 + qt, r1 = r0 + 8;
    const int colh = h * DK;

    uint32_t qf[4][4];
    #pragma unroll
    for (int ks = 0; ks < 4; ks++) {
        #pragma unroll
        for (int p = 0; p < 4; p++) {
            int rr = (p & 1) ? r1 : r0;
            int kk = ks * 16 + qc + ((p >> 1) ? 8 : 0);
            if (rr < Lq) {
                size_t off = (size_t)(b * qB + rr * qS) * DD + colh + kk;
                qf[ks][p] = *(const uint32_t*)(Q + off);
            } else qf[ks][p] = 0u;
        }
    }

    float m0 = -1e30f, m1 = -1e30f, l0 = 0.f, l1 = 0.f;
    float oacc[8][4];
    #pragma unroll
    for (int j = 0; j < 8; j++)
        #pragma unroll
        for (int q = 0; q < 4; q++) oacc[j][q] = 0.f;

    const uint32_t ldOffK = (uint32_t)(((lane & 7) + ((lane >> 3) & 1) * 8) * FA_STRIDE
                                       + ((lane >> 4) * 8) * 2);

    const int nch = Lk / 128;
    for (int ch = 0; ch < nch; ch++) {
        const int k0g = ch * 128;
        #pragma unroll
        for (int i = 0; i < 4; i++) {
            int idx = tid + (i << 8);
            int r = idx >> 3, seg = idx & 7;
            size_t src = (size_t)(b * Lk + k0g + r) * kvld + colh + seg * 8;
            uint32_t dst = sb + (uint32_t)(r * FA_STRIDE + seg * 16);
            asm volatile("cp.async.cg.shared.global [%0], [%1], 16;" :: "r"(dst + FA_K), "l"(K + src));
            asm volatile("cp.async.cg.shared.global [%0], [%1], 16;" :: "r"(dst + FA_V), "l"(V + src));
        }
        asm volatile("cp.async.commit_group;");
        if (tid < 128)
            ((float*)(smem + FA_MASK))[tid] = mask[b * Lk + k0g + tid] ? 0.f : -1e9f;
        asm volatile("cp.async.wait_group 0;");
        __syncthreads();

        float sacc[16][4];
        #pragma unroll
        for (int j = 0; j < 16; j++)
            #pragma unroll
            for (int q = 0; q < 4; q++) sacc[j][q] = 0.f;

        #pragma unroll
        for (int ks = 0; ks < 4; ks++) {
            #pragma unroll
            for (int nt = 0; nt < 8; nt++) {
                uint32_t off = ldOffK + (uint32_t)(nt * 16 * FA_STRIDE + ks * 32);
                uint32_t kh4[4];
                ldm_x4(kh4, sb + FA_K + off);
                #pragma unroll
                for (int sub = 0; sub < 2; sub++)
                    mma_f16_b(sacc[nt * 2 + sub], qf[ks], kh4[sub], kh4[sub + 2]);
            }
        }

        float cm0 = -1e30f, cm1 = -1e30f;
        #pragma unroll
        for (int j = 0; j < 16; j++) {
            int kb = j * 8 + qc;
            float b0v = sbias[kb], b1v = sbias[kb + 1];
            sacc[j][0] = sacc[j][0] * scale + b0v;
            sacc[j][1] = sacc[j][1] * scale + b1v;
            sacc[j][2] = sacc[j][2] * scale + b0v;
            sacc[j][3] = sacc[j][3] * scale + b1v;
            cm0 = fmaxf(cm0, fmaxf(sacc[j][0], sacc[j][1]));
            cm1 = fmaxf(cm1, fmaxf(sacc[j][2], sacc[j][3]));
        }
        cm0 = fmaxf(cm0, __shfl_xor_sync(0xFFFFFFFFu, cm0, 1));
        cm0 = fmaxf(cm0, __shfl_xor_sync(0xFFFFFFFFu, cm0, 2));
        cm1 = fmaxf(cm1, __shfl_xor_sync(0xFFFFFFFFu, cm1, 1));
        cm1 = fmaxf(cm1, __shfl_xor_sync(0xFFFFFFFFu, cm1, 2));
        float nm0 = fmaxf(m0, cm0), nm1 = fmaxf(m1, cm1);
        float al0 = __expf(m0 - nm0), al1 = __expf(m1 - nm1);
        m0 = nm0; m1 = nm1;

        float ps0 = 0.f, ps1 = 0.f;
        #pragma unroll
        for (int j = 0; j < 16; j++) {
            float p0 = __expf(sacc[j][0] - nm0), p1 = __expf(sacc[j][1] - nm0);
            float p2 = __expf(sacc[j][2] - nm1), p3 = __expf(sacc[j][3] - nm1);
            ps0 += p0 + p1; ps1 += p2 + p3;
            sacc[j][0] = p0; sacc[j][1] = p1; sacc[j][2] = p2; sacc[j][3] = p3;
        }
        ps0 += __shfl_xor_sync(0xFFFFFFFFu, ps0, 1);
        ps0 += __shfl_xor_sync(0xFFFFFFFFu, ps0, 2);
        ps1 += __shfl_xor_sync(0xFFFFFFFFu, ps1, 1);
        ps1 += __shfl_xor_sync(0xFFFFFFFFu, ps1, 2);
        l0 = l0 * al0 + ps0; l1 = l1 * al1 + ps1;
        #pragma unroll
        for (int j = 0; j < 8; j++) {
            oacc[j][0] *= al0; oacc[j][1] *= al0;
            oacc[j][2] *= al1; oacc[j][3] *= al1;
        }

        #pragma unroll
        for (int kk = 0; kk < 8; kk++) {
            uint32_t ahp[4], alp[4];
            #pragma unroll
            for (int jj = 0; jj < 2; jj++) {
                const float* sp = sacc[2 * kk + jj];
                f162 h01, l01, h23, l23;
                split2h(sp[0], sp[1], h01, l01);
                split2h(sp[2], sp[3], h23, l23);
                ahp[jj * 2 + 0] = *(uint32_t*)&h01; ahp[jj * 2 + 1] = *(uint32_t*)&h23;
                alp[jj * 2 + 0] = *(uint32_t*)&l01; alp[jj * 2 + 1] = *(uint32_t*)&l23;
            }
            #pragma unroll
            for (int dt = 0; dt < 4; dt++) {
                uint32_t off = ldOffK + (uint32_t)(kk * 16 * FA_STRIDE + dt * 32);
                uint32_t vh4[4];
                ldm_x4_t(vh4, sb + FA_V + off);
                #pragma unroll
                for (int sub = 0; sub < 2; sub++)
                    mma_f16_b(oacc[dt * 2 + sub], ahp, vh4[sub*2], vh4[sub*2+1]);
                #pragma unroll
                for (int sub = 0; sub < 2; sub++)
                    mma_f16_b(oacc[dt * 2 + sub], alp, vh4[sub*2], vh4[sub*2+1]);
            }
        }
        __syncthreads();
    }

    float inv0 = 1.f / l0, inv1 = 1.f / l1;
    #pragma unroll
    for (int j = 0; j < 8; j++) {
        int col = colh + j * 8 + qc;
        if (r0 < Lq) {
            size_t off = (size_t)(b * oB + r0) * DD + col;
            *(f162*)(O + off) = __halves2half2(__float2half_rn(oacc[j][0] * inv0),
                                               __float2half_rn(oacc[j][1] * inv0));
        }
        if (r1 < Lq) {
            size_t off = (size_t)(b * oB + r1) * DD + col;
            *(f162*)(O + off) = __halves2half2(__float2half_rn(oacc[j][2] * inv1),
                                               __float2half_rn(oacc[j][3] * inv1));
        }
    }
}

// ------- LayerNorm: warp per row, single pass, register resident ------------
__global__ __launch_bounds__(256)
void ln_warp(const float* __restrict__ x, float* __restrict__ y,
             f16* __restrict__ yh,
             const float* __restrict__ g, const float* __restrict__ be)
{
    const int lane = threadIdx.x & 31;
    const size_t row = (size_t)(blockIdx.x * 8) + (threadIdx.x >> 5);
    const float* xr = x + row * DD;

    float4 v[6];
    float s = 0.f, s2 = 0.f;
    #pragma unroll
    for (int i = 0; i < 6; i++) {
        v[i] = *(const float4*)&xr[i * 128 + lane * 4];
        s  += v[i].x + v[i].y + v[i].z + v[i].w;
        s2 += v[i].x * v[i].x + v[i].y * v[i].y + v[i].z * v[i].z + v[i].w * v[i].w;
    }
    #pragma unroll
    for (int o = 16; o > 0; o >>= 1) {
        s  += __shfl_xor_sync(0xFFFFFFFFu, s, o);
        s2 += __shfl_xor_sync(0xFFFFFFFFu, s2, o);
    }
    const float mean = s * (1.f / DD);
    const float var  = s2 * (1.f / DD) - mean * mean;
    const float rstd = rsqrtf(var + 1e-5f);

    #pragma unroll
    for (int i = 0; i < 6; i++) {
        int col = i * 128 + lane * 4;
        float4 gv = *(const float4*)&g[col];
        float4 bv = *(const float4*)&be[col];
        float4 o;
        o.x = (v[i].x - mean) * rstd * gv.x + bv.x;
        o.y = (v[i].y - mean) * rstd * gv.y + bv.y;
        o.z = (v[i].z - mean) * rstd * gv.z + bv.z;
        o.w = (v[i].w - mean) * rstd * gv.w + bv.w;
        if (y) *(float4*)&y[row * DD + col] = o;
        if (yh) {
            *(f162*)&yh[row * DD + col] =
                __halves2half2(__float2half_rn(o.x), __float2half_rn(o.y));
            *(f162*)&yh[row * DD + col + 2] =
                __halves2half2(__float2half_rn(o.z), __float2half_rn(o.w));
        }
    }
}

// ---------------- va = fea_slots[S,B,D] + proj1[B,S,D] transposed -----------
__global__ __launch_bounds__(256)
void va_kernel(const float* __restrict__ slots, const float* __restrict__ proj,
               float* __restrict__ va)
{
    int idx = blockIdx.x * 256 + threadIdx.x;
    if (idx >= SS * BB * DD) return;
    int d = idx % DD;
    int r = idx / DD;
    int s = r / BB, b = r % BB;
    va[idx] = slots[idx] + proj[((long long)b * SS + s) * DD + d];
}

// ---------------- host-side helpers ----------------------------------------
template<typename T>
static T* sym(const void* s) { void* p = nullptr; cudaGetSymbolAddress(&p, s); return (T*)p; }

static void run_lin_s(cudaStream_t st, const f16* A, const f16* W,
                      float* C, int M, int N, int K,
                      const float* bias, const float* res, int relu,
                      f16* Ch = nullptr)
{
    int ctas128 = (N / 128) * ((M + 127) / 128);
    if (M <= 4096 && ctas128 < 232) {
        dim3 grid(N / 128, (M + 63) / 64);
        mma_gemm<64><<<grid, 256, 2 * STG64, st>>>(A, W, C, M, N, K, bias, res, relu, Ch);
    } else {
        dim3 grid(N / 128, (M + 127) / 128);
        mma_gemm<128><<<grid, 256, 2 * STG128, st>>>(A, W, C, M, N, K, bias, res, relu, Ch);
    }
}

extern "C" void kernel_launch(void* const* d_in, const int* in_sizes, int n_in,
                              void* d_out, int out_size)
{
    static bool s_init = false;
    static cudaStream_t s1, s2;
    static cudaEvent_t e0, e1, e2;
    if (!s_init) {
        cudaFuncSetAttribute(mma_gemm<128>, cudaFuncAttributeMaxDynamicSharedMemorySize, 2 * STG128);
        cudaFuncSetAttribute(mma_gemm<64>,  cudaFuncAttributeMaxDynamicSharedMemorySize, 2 * STG64);
        cudaFuncSetAttribute(flash_attn, cudaFuncAttributeMaxDynamicSharedMemorySize, FA_SMEM);
        cudaStreamCreateWithFlags(&s1, cudaStreamNonBlocking);
        cudaStreamCreateWithFlags(&s2, cudaStreamNonBlocking);
        cudaEventCreateWithFlags(&e0, cudaEventDisableTiming);
        cudaEventCreateWithFlags(&e1, cudaEventDisableTiming);
        cudaEventCreateWithFlags(&e2, cudaEventDisableTiming);
        s_init = true;
    }

    const float* cur_raw  = (const float*)d_in[0];
    const float* ctx_raw  = (const float*)d_in[1];
    const float* pre_raw  = (const float*)d_in[2];
    const int*   ctx_mask = (const int*)d_in[3];
    const int*   utt_mask = (const int*)d_in[4];
    const float* norm_W   = (const float*)d_in[5];
    const float* norm_b   = (const float*)d_in[6];
    const float* norm_g   = (const float*)d_in[7];
    const float* norm_be  = (const float*)d_in[8];
    const float* Wq = (const float*)d_in[9];
    const float* bq = (const float*)d_in[10];
    const float* Wk = (const float*)d_in[11];
    const float* bk = (const float*)d_in[12];
    const float* Wv = (const float*)d_in[13];
    const float* bv = (const float*)d_in[14];
    const float* Wo = (const float*)d_in[15];
    const float* bo = (const float*)d_in[16];
    const float* ln_g = (const float*)d_in[17];
    const float* ln_b = (const float*)d_in[18];
    const float* W1 = (const float*)d_in[19];
    const float* b1 = (const float*)d_in[20];
    const float* W2 = (const float*)d_in[21];
    const float* b2 = (const float*)d_in[22];

    float* out  = (float*)d_out;
    float* cur_out   = out;
    float* slots_out = out + (long long)BB * LU * DD;

    float* fea_cur   = sym<float>(g_fea_cur);
    float* fea_ctx   = sym<float>(g_fea_ctx);
    float* fea_slots = sym<float>(g_fea_slots);
    float* cur_attn  = sym<float>(g_cur_attn);
    float* proj1 = sym<float>(g_proj1);
    float* va = sym<float>(g_va);
    float* bkv0 = sym<float>(g_bkv0);
    float* bkv1 = sym<float>(g_bkv1);

    f16 *wn = sym<f16>(g_wn);
    f16 *wq = sym<f16>(g_wq);
    f16 *wkv0 = sym<f16>(g_wkv0);
    f16 *wkv1 = sym<f16>(g_wkv1);
    f16 *wo = sym<f16>(g_wo);
    f16 *w1 = sym<f16>(g_w1);
    f16 *w2 = sym<f16>(g_w2);
    f16 *xcur = sym<f16>(g_xcur);
    f16 *xctx = sym<f16>(g_xctx);
    f16 *xpre = sym<f16>(g_xpre);
    f16 *fc = sym<f16>(g_fc);
    f16 *fx = sym<f16>(g_fx);
    f16 *fs = sym<f16>(g_fs);
    f16 *lnb = sym<f16>(g_lnb);
    f16 *ffh = sym<f16>(g_ffh);
    f16 *a0 = sym<f16>(g_a0);
    f16 *a1 = sym<f16>(g_a1);
    f16 *co = sym<f16>(g_co);
    f16 *q0 = sym<f16>(g_q0);
    f16 *kv0 = sym<f16>(g_kv0);
    f16 *q1 = sym<f16>(g_q1);
    f16 *kv1 = sym<f16>(g_kv1);

    const int DxD = DD * DD;
    const int N2 = 2 * DD;

    // ---- packed biases
    cudaMemcpyAsync(bkv0,      bk,      DD * 4, cudaMemcpyDeviceToDevice, 0);
    cudaMemcpyAsync(bkv0 + DD, bv,      DD * 4, cudaMemcpyDeviceToDevice, 0);
    cudaMemcpyAsync(bkv1,      bk + DD, DD * 4, cudaMemcpyDeviceToDevice, 0);
    cudaMemcpyAsync(bkv1 + DD, bv + DD, DD * 4, cudaMemcpyDeviceToDevice, 0);

    // ---- one launch for ALL fp32->f16 conversions (with KV weight packing)
    {
        ConvArgs ca;
        const float* xs[NSEG] = { norm_W, Wq, Wo, W1, W2,
                                  Wk, Wv, Wk + DxD, Wv + DxD,
                                  cur_raw, ctx_raw, pre_raw };
        f16* hs[NSEG] = { wn, wq, wo, w1, w2,
                          wkv0, wkv0, wkv1, wkv1,
                          xcur, xctx, xpre };
        int ns[NSEG] = { 3*DxD/4, 2*DxD/4, 2*DxD/4, 2*DD*DFF/4, 2*DFF*DD/4,
                         DxD/4, DxD/4, DxD/4, DxD/4,
                         BB*LU*DD/4, BB*LC*DD/4, SS*BB*DD/4 };
        int ld4[NSEG] = { 192, 192, 192, 192, 192, 384, 384, 384, 384, 192, 192, 192 };
        int co4[NSEG] = { 0, 0, 0, 0, 0, 0, 192, 0, 192, 0, 0, 0 };
        for (int i = 0; i < NSEG; i++) {
            ca.x[i]=xs[i]; ca.h[i]=hs[i];
            ca.n4[i]=ns[i]; ca.ldo4[i]=ld4[i]; ca.coff4[i]=co4[i];
        }
        conv_multi<<<dim3(128, NSEG), 256>>>(ca);
    }
    cudaEventRecord(e0, 0);
    cudaStreamWaitEvent(s1, e0, 0);
    cudaStreamWaitEvent(s2, e0, 0);

    // ---- s1: cur chain (norm -> LN -> Q0)
    run_lin_s(s1, xcur, wn, fea_cur, BB * LU, DD, DD, norm_b, nullptr, 0);
    ln_warp<<<BB * LU / 8, 256, 0, s1>>>(fea_cur, fea_cur, fc, norm_g, norm_be);
    run_lin_s(s1, fc, wq, nullptr, BB * LU, DD, DD, bq, nullptr, 0, q0);
    cudaEventRecord(e1, s1);

    // ---- s2: slots chain (norm -> LN -> Q1)
    run_lin_s(s2, xpre, wn + 2 * DxD, fea_slots, SS * BB, DD, DD,
              norm_b + 2 * DD, nullptr, 0);
    ln_warp<<<SS * BB / 8, 256, 0, s2>>>(fea_slots, fea_slots, fs,
                                         norm_g + 2 * DD, norm_be + 2 * DD);
    run_lin_s(s2, fs, wq + DxD, nullptr, SS * BB, DD, DD, bq + DD, nullptr, 0, q1);
    cudaEventRecord(e2, s2);

    // ---- main: ctx chain (norm -> LN -> fused K0|V0)
    run_lin_s(0, xctx, wn + DxD, fea_ctx, BB * LC, DD, DD, norm_b + DD, nullptr, 0);
    ln_warp<<<BB * LC / 8, 256>>>(fea_ctx, nullptr, fx, norm_g + DD, norm_be + DD);
    run_lin_s(0, fx, wkv0, nullptr, BB * LC, N2, DD, bkv0, nullptr, 0, kv0);

    cudaStreamWaitEvent(0, e1, 0);

    // ---- stage B (main)
    flash_attn<<<BB * HH, 256, FA_SMEM>>>(q0, kv0, kv0 + DD, ctx_mask, a0,
                                          LU, LC, LU, 1, LU, N2, 0.125f);
    run_lin_s(0, a0, wo, cur_attn, BB * LU, DD, DD, bo, fea_cur, 0);
    ln_warp<<<BB * LU / 8, 256>>>(cur_attn, nullptr, lnb, ln_g, ln_b);
    run_lin_s(0, lnb, w1, nullptr, BB * LU, DFF, DD, b1, nullptr, 1, ffh);
    run_lin_s(0, ffh, w2, cur_out, BB * LU, DD, DFF, b2, cur_attn, 0, co);

    // ---- stage C (main): fused K1|V1
    run_lin_s(0, co, wkv1, nullptr, BB * LU, N2, DD, bkv1, nullptr, 0, kv1);

    cudaStreamWaitEvent(0, e2, 0);

    flash_attn<<<BB * HH, 256, FA_SMEM>>>(q1, kv1, kv1 + DD, utt_mask, a1,
                                          SS, LU, 1, BB, SS, N2, 0.125f);

    run_lin_s(0, a1, wo + DxD, proj1, BB * SS, DD, DD, bo + DD, nullptr, 0);
    va_kernel<<<(SS * BB * DD + 255) / 256, 256>>>(fea_slots, proj1, va);

    ln_warp<<<SS * BB / 8, 256>>>(va, nullptr, lnb, ln_g + DD, ln_b + DD);
    run_lin_s(0, lnb, w1 + DD * DFF, nullptr, SS * BB, DFF, DD, b1 + DFF, nullptr, 1, ffh);
    run_lin_s(0, ffh, w2 + DFF * DD, slots_out, SS * BB, DD, DFF, b2 + DD, va, 0);
}

// round 14
// speedup vs baseline: 1.4849x; 1.0906x over previous
#include <cuda_runtime.h>
#include <cuda_fp16.h>
#include <cstdint>

// Problem dims
#define BB   32
#define LU   128
#define LC   512
#define SS   30
#define DD   768
#define HH   12
#define DK   64
#define DFF  1152

typedef __half  f16;
typedef __half2 f162;

// ---------------- fp32 scratch ----------------------------------------------
__device__ __align__(256) float g_fea_cur[BB*LU*DD];
__device__ __align__(256) float g_fea_ctx[BB*LC*DD];
__device__ __align__(256) float g_fea_slots[SS*BB*DD];
__device__ __align__(256) float g_cur_attn[BB*LU*DD];
__device__ __align__(256) float g_va[SS*BB*DD];
__device__ __align__(256) float g_bkv0[2*DD];
__device__ __align__(256) float g_bkv1[2*DD];

// ---------------- f16 scratch (single precision everywhere) -----------------
__device__ __align__(256) f16 g_wn[3*DD*DD];
__device__ __align__(256) f16 g_wq[2*DD*DD];
__device__ __align__(256) f16 g_wkv0[DD*2*DD];
__device__ __align__(256) f16 g_wkv1[DD*2*DD];
__device__ __align__(256) f16 g_wo[2*DD*DD];
__device__ __align__(256) f16 g_w1[2*DD*DFF];
__device__ __align__(256) f16 g_w2[2*DFF*DD];
__device__ __align__(256) f16 g_xcur[BB*LU*DD];
__device__ __align__(256) f16 g_xctx[BB*LC*DD];
__device__ __align__(256) f16 g_xpre[SS*BB*DD];
__device__ __align__(256) f16 g_fc[BB*LU*DD];
__device__ __align__(256) f16 g_fx[BB*LC*DD];
__device__ __align__(256) f16 g_fs[SS*BB*DD];
__device__ __align__(256) f16 g_lnb[BB*LU*DD];
__device__ __align__(256) f16 g_ffh[BB*LU*DFF];
__device__ __align__(256) f16 g_a0[BB*LU*DD];
__device__ __align__(256) f16 g_a1[BB*SS*DD];
__device__ __align__(256) f16 g_co[BB*LU*DD];
__device__ __align__(256) f16 g_q0[BB*LU*DD];
__device__ __align__(256) f16 g_kv0[BB*LC*2*DD];
__device__ __align__(256) f16 g_q1[SS*BB*DD];
__device__ __align__(256) f16 g_kv1[BB*LU*2*DD];

// =================== helpers ================================================
__device__ __forceinline__ uint32_t smem_u32(const void* p) {
    uint32_t a;
    asm("{ .reg .u64 t; cvta.to.shared.u64 t, %1; cvt.u32.u64 %0, t; }" : "=r"(a) : "l"(p));
    return a;
}
__device__ __forceinline__ void ldm_x4(uint32_t* r, uint32_t addr) {
    asm volatile("ldmatrix.sync.aligned.m8n8.x4.shared.b16 {%0,%1,%2,%3}, [%4];"
                 : "=r"(r[0]), "=r"(r[1]), "=r"(r[2]), "=r"(r[3]) : "r"(addr));
}
__device__ __forceinline__ void ldm_x4_t(uint32_t* r, uint32_t addr) {
    asm volatile("ldmatrix.sync.aligned.m8n8.x4.trans.shared.b16 {%0,%1,%2,%3}, [%4];"
                 : "=r"(r[0]), "=r"(r[1]), "=r"(r[2]), "=r"(r[3]) : "r"(addr));
}
__device__ __forceinline__ void mma_f16(float* c, const uint32_t* a, const uint32_t* b) {
    asm volatile("mma.sync.aligned.m16n8k16.row.col.f32.f16.f16.f32 "
                 "{%0,%1,%2,%3}, {%4,%5,%6,%7}, {%8,%9}, {%0,%1,%2,%3};"
                 : "+f"(c[0]), "+f"(c[1]), "+f"(c[2]), "+f"(c[3])
                 : "r"(a[0]), "r"(a[1]), "r"(a[2]), "r"(a[3]), "r"(b[0]), "r"(b[1]));
}
__device__ __forceinline__ void mma_f16_b(float* c, const uint32_t* a, uint32_t b0, uint32_t b1) {
    asm volatile("mma.sync.aligned.m16n8k16.row.col.f32.f16.f16.f32 "
                 "{%0,%1,%2,%3}, {%4,%5,%6,%7}, {%8,%9}, {%0,%1,%2,%3};"
                 : "+f"(c[0]), "+f"(c[1]), "+f"(c[2]), "+f"(c[3])
                 : "r"(a[0]), "r"(a[1]), "r"(a[2]), "r"(a[3]), "r"(b0), "r"(b1));
}
__device__ __forceinline__ void split2h(float x, float y, f162& h, f162& l) {
    f16 hx = __float2half_rn(x), hy = __float2half_rn(y);
    h = __halves2half2(hx, hy);
    l = __halves2half2(__float2half_rn(x - __half2float(hx)),
                       __float2half_rn(y - __half2float(hy)));
}

// --------- merged fp32 -> f16 converter, with column packing ----------------
#define NSEG 12
struct ConvArgs {
    const float* x[NSEG];
    f16* h[NSEG];
    int n4[NSEG];
    int ldo4[NSEG];
    int coff4[NSEG];
};
__global__ __launch_bounds__(256)
void conv_multi(ConvArgs a)
{
    int s = blockIdx.y;
    int n4 = a.n4[s];
    const float* x = a.x[s];
    f16* h = a.h[s];
    int ldo4 = a.ldo4[s], coff4 = a.coff4[s];
    int stride = gridDim.x * 256;
    for (int i = blockIdx.x * 256 + threadIdx.x; i < n4; i += stride) {
        float4 v = ((const float4*)x)[i];
        f162 h01 = __halves2half2(__float2half_rn(v.x), __float2half_rn(v.y));
        f162 h23 = __halves2half2(__float2half_rn(v.z), __float2half_rn(v.w));
        int o4 = (i / 192) * ldo4 + coff4 + (i % 192);
        ((f162*)h)[2*o4]   = h01;
        ((f162*)h)[2*o4+1] = h23;
    }
}

// ------------- pack KV biases in one kernel (replaces 4 memcpy nodes) -------
__global__ __launch_bounds__(256)
void pack_bias(const float* __restrict__ bk, const float* __restrict__ bv,
               float* __restrict__ bkv0, float* __restrict__ bkv1)
{
    int i = blockIdx.x * 256 + threadIdx.x;
    if (i >= DD) return;
    bkv0[i]      = bk[i];
    bkv0[DD + i] = bv[i];
    bkv1[i]      = bk[DD + i];
    bkv1[DD + i] = bv[DD + i];
}

// ========= single-f16 HMMA GEMM, KC=32, 2-stage cp.async ====================
// trans!=0: output row r (= b*SS+s) redirected to tr = (r%SS)*BB + r/SS for
// both the residual read and the C write (fuses the [B,S,D]->[S,B,D] add).
#define A_STRIDE 80
#define B_STRIDE 272
#define KC 32
#define B_TILE 8704            // 32 * 272

template<int MT>
__device__ __forceinline__ void stage_load(
    uint32_t stg, const f16* __restrict__ A, const f16* __restrict__ B,
    int m0, int n0, int kc0, int M, int N, int K, int tid)
{
    constexpr int SA = MT * A_STRIDE;
    #pragma unroll
    for (int i = 0; i < MT / 64; i++) {
        int ca = tid + (i << 8);
        int r = ca >> 2, seg = ca & 3;
        int m = m0 + r;
        uint32_t dst = stg + (uint32_t)(r * A_STRIDE + seg * 16);
        int sz = (m < M) ? 16 : 0;
        size_t so = (size_t)m * K + kc0 + seg * 8;
        asm volatile("cp.async.cg.shared.global [%0], [%1], 16, %2;"
                     :: "r"(dst), "l"(A + so), "r"(sz));
    }
    #pragma unroll
    for (int i = 0; i < 2; i++) {
        int cb = tid + (i << 8);
        int r = cb >> 4, seg = cb & 15;
        uint32_t dst = stg + (uint32_t)(SA + r * B_STRIDE + seg * 16);
        size_t so = (size_t)(kc0 + r) * N + n0 + seg * 8;
        asm volatile("cp.async.cg.shared.global [%0], [%1], 16;"
                     :: "r"(dst), "l"(B + so));
    }
    asm volatile("cp.async.commit_group;");
}

template<int MT>
__global__ void __launch_bounds__(256, 3)
mma_gemm(const f16* __restrict__ A, const f16* __restrict__ B,
         float* __restrict__ C, int M, int N, int K,
         const float* __restrict__ bias, const float* __restrict__ res, int relu,
         f16* __restrict__ Ch, int trans)
{
    constexpr int SA  = MT * A_STRIDE;
    constexpr int TSTG = SA + B_TILE;
    constexpr int WM = (MT == 128) ? 4 : 2;
    constexpr int NP = (MT == 128) ? 4 : 2;

    extern __shared__ __align__(128) char smem[];
    const uint32_t sb = smem_u32(smem);
    const int tid = threadIdx.x;
    const int wid = tid >> 5, lane = tid & 31;
    const int m0 = blockIdx.y * MT, n0 = blockIdx.x * 128;
    const int mw = (wid % WM) * 32;
    const int nw = (wid / WM) * (NP * 16);

    float acc[2][NP * 2][4];
    #pragma unroll
    for (int i = 0; i < 2; i++)
        #pragma unroll
        for (int j = 0; j < NP * 2; j++)
            #pragma unroll
            for (int q = 0; q < 4; q++) acc[i][j][q] = 0.f;

    const int lsub = lane >> 3, lr = lane & 7;
    const uint32_t aOff = (uint32_t)((lr + (lsub & 1) * 8) * A_STRIDE + (lsub >> 1) * 16);
    const uint32_t bOff = (uint32_t)((lr + (lsub & 1) * 8) * B_STRIDE + (lsub >> 1) * 16);

    const int nc = K / KC;
    stage_load<MT>(sb, A, B, m0, n0, 0, M, N, K, tid);

    for (int c = 0; c < nc; c++) {
        if (c + 1 < nc) {
            stage_load<MT>(sb + ((c + 1) & 1) * TSTG, A, B,
                           m0, n0, (c + 1) * KC, M, N, K, tid);
            asm volatile("cp.async.wait_group 1;");
        } else {
            asm volatile("cp.async.wait_group 0;");
        }
        __syncthreads();

        const uint32_t st = sb + (c & 1) * TSTG;
        #pragma unroll
        for (int ks = 0; ks < KC; ks += 16) {
            uint32_t ah[2][4];
            #pragma unroll
            for (int mi = 0; mi < 2; mi++) {
                uint32_t off = aOff + (uint32_t)((mw + mi * 16) * A_STRIDE + ks * 2);
                ldm_x4(ah[mi], st + off);
            }
            #pragma unroll
            for (int np = 0; np < NP; np++) {
                uint32_t off = bOff + (uint32_t)(ks * B_STRIDE + (nw + np * 16) * 2);
                uint32_t bh[4];
                ldm_x4_t(bh, st + SA + off);
                #pragma unroll
                for (int mi = 0; mi < 2; mi++)
                    #pragma unroll
                    for (int g2 = 0; g2 < 2; g2++)
                        mma_f16(acc[mi][np * 2 + g2], ah[mi], bh + g2 * 2);
            }
        }
        __syncthreads();
    }

    // ---- epilogue
    const int qrow = lane >> 2, qcol = (lane & 3) * 2;
    #pragma unroll
    for (int mi = 0; mi < 2; mi++) {
        int r0 = m0 + mw + mi * 16 + qrow;
        #pragma unroll
        for (int ni = 0; ni < NP * 2; ni++) {
            int cidx = n0 + nw + ni * 8 + qcol;
            float* a = acc[mi][ni];
            #pragma unroll
            for (int hh = 0; hh < 2; hh++) {
                int r = r0 + hh * 8;
                if (r >= M) continue;
                int ro = trans ? ((r % SS) * BB + r / SS) : r;
                float x = a[hh * 2 + 0] + bias[cidx];
                float y = a[hh * 2 + 1] + bias[cidx + 1];
                if (relu) { x = fmaxf(x, 0.f); y = fmaxf(y, 0.f); }
                if (res) {
                    const float2 rv = *(const float2*)&res[(size_t)ro * N + cidx];
                    x += rv.x; y += rv.y;
                }
                if (C) {
                    float2 o; o.x = x; o.y = y;
                    *(float2*)&C[(size_t)ro * N + cidx] = o;
                }
                if (Ch) {
                    *(f162*)&Ch[(size_t)ro * N + cidx] =
                        __halves2half2(__float2half_rn(x), __float2half_rn(y));
                }
            }
        }
    }
}

#define STG128 (128 * A_STRIDE + B_TILE)
#define STG64  (64  * A_STRIDE + B_TILE)

// ====== fused flash attention (single Q/K/V, P split in regs for PV) ========
#define FA_STRIDE 144
#define FA_K 0
#define FA_V 18432
#define FA_MASK 36864
#define FA_SMEM (FA_MASK + 512)

__global__ void __launch_bounds__(256)
flash_attn(const f16* __restrict__ Q, const f16* __restrict__ K,
           const f16* __restrict__ V, const int* __restrict__ mask,
           f16* __restrict__ O,
           int Lq, int Lk, int qB, int qS, int oB, int kvld, float scale)
{
    extern __shared__ __align__(128) char smem[];
    const uint32_t sb = smem_u32(smem);
    const float* sbias = (const float*)(smem + FA_MASK);
    const int tid = threadIdx.x, wid = tid >> 5, lane = tid & 31;
    const int z = blockIdx.x, b = z / HH, h = z % HH;
    const int qt = lane >> 2, qc = (lane & 3) * 2;
    const int r0 = wid * 16 + qt, r1 = r0 + 8;
    const int colh = h * DK;

    uint32_t qf[4][4];
    #pragma unroll
    for (int ks = 0; ks < 4; ks++) {
        #pragma unroll
        for (int p = 0; p < 4; p++) {
            int rr = (p & 1) ? r1 : r0;
            int kk = ks * 16 + qc + ((p >> 1) ? 8 : 0);
            if (rr < Lq) {
                size_t off = (size_t)(b * qB + rr * qS) * DD + colh + kk;
                qf[ks][p] = *(const uint32_t*)(Q + off);
            } else qf[ks][p] = 0u;
        }
    }

    float m0 = -1e30f, m1 = -1e30f, l0 = 0.f, l1 = 0.f;
    float oacc[8][4];
    #pragma unroll
    for (int j = 0; j < 8; j++)
        #pragma unroll
        for (int q = 0; q < 4; q++) oacc[j][q] = 0.f;

    const uint32_t ldOffK = (uint32_t)(((lane & 7) + ((lane >> 3) & 1) * 8) * FA_STRIDE
                                       + ((lane >> 4) * 8) * 2);

    const int nch = Lk / 128;
    for (int ch = 0; ch < nch; ch++) {
        const int k0g = ch * 128;
        #pragma unroll
        for (int i = 0; i < 4; i++) {
            int idx = tid + (i << 8);
            int r = idx >> 3, seg = idx & 7;
            size_t src = (size_t)(b * Lk + k0g + r) * kvld + colh + seg * 8;
            uint32_t dst = sb + (uint32_t)(r * FA_STRIDE + seg * 16);
            asm volatile("cp.async.cg.shared.global [%0], [%1], 16;" :: "r"(dst + FA_K), "l"(K + src));
            asm volatile("cp.async.cg.shared.global [%0], [%1], 16;" :: "r"(dst + FA_V), "l"(V + src));
        }
        asm volatile("cp.async.commit_group;");
        if (tid < 128)
            ((float*)(smem + FA_MASK))[tid] = mask[b * Lk + k0g + tid] ? 0.f : -1e9f;
        asm volatile("cp.async.wait_group 0;");
        __syncthreads();

        float sacc[16][4];
        #pragma unroll
        for (int j = 0; j < 16; j++)
            #pragma unroll
            for (int q = 0; q < 4; q++) sacc[j][q] = 0.f;

        #pragma unroll
        for (int ks = 0; ks < 4; ks++) {
            #pragma unroll
            for (int nt = 0; nt < 8; nt++) {
                uint32_t off = ldOffK + (uint32_t)(nt * 16 * FA_STRIDE + ks * 32);
                uint32_t kh4[4];
                ldm_x4(kh4, sb + FA_K + off);
                #pragma unroll
                for (int sub = 0; sub < 2; sub++)
                    mma_f16_b(sacc[nt * 2 + sub], qf[ks], kh4[sub], kh4[sub + 2]);
            }
        }

        float cm0 = -1e30f, cm1 = -1e30f;
        #pragma unroll
        for (int j = 0; j < 16; j++) {
            int kb = j * 8 + qc;
            float b0v = sbias[kb], b1v = sbias[kb + 1];
            sacc[j][0] = sacc[j][0] * scale + b0v;
            sacc[j][1] = sacc[j][1] * scale + b1v;
            sacc[j][2] = sacc[j][2] * scale + b0v;
            sacc[j][3] = sacc[j][3] * scale + b1v;
            cm0 = fmaxf(cm0, fmaxf(sacc[j][0], sacc[j][1]));
            cm1 = fmaxf(cm1, fmaxf(sacc[j][2], sacc[j][3]));
        }
        cm0 = fmaxf(cm0, __shfl_xor_sync(0xFFFFFFFFu, cm0, 1));
        cm0 = fmaxf(cm0, __shfl_xor_sync(0xFFFFFFFFu, cm0, 2));
        cm1 = fmaxf(cm1, __shfl_xor_sync(0xFFFFFFFFu, cm1, 1));
        cm1 = fmaxf(cm1, __shfl_xor_sync(0xFFFFFFFFu, cm1, 2));
        float nm0 = fmaxf(m0, cm0), nm1 = fmaxf(m1, cm1);
        float al0 = __expf(m0 - nm0), al1 = __expf(m1 - nm1);
        m0 = nm0; m1 = nm1;

        float ps0 = 0.f, ps1 = 0.f;
        #pragma unroll
        for (int j = 0; j < 16; j++) {
            float p0 = __expf(sacc[j][0] - nm0), p1 = __expf(sacc[j][1] - nm0);
            float p2 = __expf(sacc[j][2] - nm1), p3 = __expf(sacc[j][3] - nm1);
            ps0 += p0 + p1; ps1 += p2 + p3;
            sacc[j][0] = p0; sacc[j][1] = p1; sacc[j][2] = p2; sacc[j][3] = p3;
        }
        ps0 += __shfl_xor_sync(0xFFFFFFFFu, ps0, 1);
        ps0 += __shfl_xor_sync(0xFFFFFFFFu, ps0, 2);
        ps1 += __shfl_xor_sync(0xFFFFFFFFu, ps1, 1);
        ps1 += __shfl_xor_sync(0xFFFFFFFFu, ps1, 2);
        l0 = l0 * al0 + ps0; l1 = l1 * al1 + ps1;
        #pragma unroll
        for (int j = 0; j < 8; j++) {
            oacc[j][0] *= al0; oacc[j][1] *= al0;
            oacc[j][2] *= al1; oacc[j][3] *= al1;
        }

        #pragma unroll
        for (int kk = 0; kk < 8; kk++) {
            uint32_t ahp[4], alp[4];
            #pragma unroll
            for (int jj = 0; jj < 2; jj++) {
                const float* sp = sacc[2 * kk + jj];
                f162 h01, l01, h23, l23;
                split2h(sp[0], sp[1], h01, l01);
                split2h(sp[2], sp[3], h23, l23);
                ahp[jj * 2 + 0] = *(uint32_t*)&h01; ahp[jj * 2 + 1] = *(uint32_t*)&h23;
                alp[jj * 2 + 0] = *(uint32_t*)&l01; alp[jj * 2 + 1] = *(uint32_t*)&l23;
            }
            #pragma unroll
            for (int dt = 0; dt < 4; dt++) {
                uint32_t off = ldOffK + (uint32_t)(kk * 16 * FA_STRIDE + dt * 32);
                uint32_t vh4[4];
                ldm_x4_t(vh4, sb + FA_V + off);
                #pragma unroll
                for (int sub = 0; sub < 2; sub++)
                    mma_f16_b(oacc[dt * 2 + sub], ahp, vh4[sub*2], vh4[sub*2+1]);
                #pragma unroll
                for (int sub = 0; sub < 2; sub++)
                    mma_f16_b(oacc[dt * 2 + sub], alp, vh4[sub*2], vh4[sub*2+1]);
            }
        }
        __syncthreads();
    }

    float inv0 = 1.f / l0, inv1 = 1.f / l1;
    #pragma unroll
    for (int j = 0; j < 8; j++) {
        int col = colh + j * 8 + qc;
        if (r0 < Lq) {
            size_t off = (size_t)(b * oB + r0) * DD + col;
            *(f162*)(O + off) = __halves2half2(__float2half_rn(oacc[j][0] * inv0),
                                               __float2half_rn(oacc[j][1] * inv0));
        }
        if (r1 < Lq) {
            size_t off = (size_t)(b * oB + r1) * DD + col;
            *(f162*)(O + off) = __halves2half2(__float2half_rn(oacc[j][2] * inv1),
                                               __float2half_rn(oacc[j][3] * inv1));
        }
    }
}

// ------- LayerNorm: warp per row, single pass, register resident ------------
__global__ __launch_bounds__(256)
void ln_warp(const float* __restrict__ x, float* __restrict__ y,
             f16* __restrict__ yh,
             const float* __restrict__ g, const float* __restrict__ be)
{
    const int lane = threadIdx.x & 31;
    const size_t row = (size_t)(blockIdx.x * 8) + (threadIdx.x >> 5);
    const float* xr = x + row * DD;

    float4 v[6];
    float s = 0.f, s2 = 0.f;
    #pragma unroll
    for (int i = 0; i < 6; i++) {
        v[i] = *(const float4*)&xr[i * 128 + lane * 4];
        s  += v[i].x + v[i].y + v[i].z + v[i].w;
        s2 += v[i].x * v[i].x + v[i].y * v[i].y + v[i].z * v[i].z + v[i].w * v[i].w;
    }
    #pragma unroll
    for (int o = 16; o > 0; o >>= 1) {
        s  += __shfl_xor_sync(0xFFFFFFFFu, s, o);
        s2 += __shfl_xor_sync(0xFFFFFFFFu, s2, o);
    }
    const float mean = s * (1.f / DD);
    const float var  = s2 * (1.f / DD) - mean * mean;
    const float rstd = rsqrtf(var + 1e-5f);

    #pragma unroll
    for (int i = 0; i < 6; i++) {
        int col = i * 128 + lane * 4;
        float4 gv = *(const float4*)&g[col];
        float4 bv = *(const float4*)&be[col];
        float4 o;
        o.x = (v[i].x - mean) * rstd * gv.x + bv.x;
        o.y = (v[i].y - mean) * rstd * gv.y + bv.y;
        o.z = (v[i].z - mean) * rstd * gv.z + bv.z;
        o.w = (v[i].w - mean) * rstd * gv.w + bv.w;
        if (y) *(float4*)&y[row * DD + col] = o;
        if (yh) {
            *(f162*)&yh[row * DD + col] =
                __halves2half2(__float2half_rn(o.x), __float2half_rn(o.y));
            *(f162*)&yh[row * DD + col + 2] =
                __halves2half2(__float2half_rn(o.z), __float2half_rn(o.w));
        }
    }
}

// ---------------- host-side helpers ----------------------------------------
template<typename T>
static T* sym(const void* s) { void* p = nullptr; cudaGetSymbolAddress(&p, s); return (T*)p; }

static void run_lin_s(cudaStream_t st, const f16* A, const f16* W,
                      float* C, int M, int N, int K,
                      const float* bias, const float* res, int relu,
                      f16* Ch = nullptr, int trans = 0)
{
    int ctas128 = (N / 128) * ((M + 127) / 128);
    if (M <= 4096 && ctas128 < 232) {
        dim3 grid(N / 128, (M + 63) / 64);
        mma_gemm<64><<<grid, 256, 2 * STG64, st>>>(A, W, C, M, N, K, bias, res, relu, Ch, trans);
    } else {
        dim3 grid(N / 128, (M + 127) / 128);
        mma_gemm<128><<<grid, 256, 2 * STG128, st>>>(A, W, C, M, N, K, bias, res, relu, Ch, trans);
    }
}

extern "C" void kernel_launch(void* const* d_in, const int* in_sizes, int n_in,
                              void* d_out, int out_size)
{
    static bool s_init = false;
    static cudaStream_t s1, s2;
    static cudaEvent_t e0, e1, e2;
    if (!s_init) {
        cudaFuncSetAttribute(mma_gemm<128>, cudaFuncAttributeMaxDynamicSharedMemorySize, 2 * STG128);
        cudaFuncSetAttribute(mma_gemm<64>,  cudaFuncAttributeMaxDynamicSharedMemorySize, 2 * STG64);
        cudaFuncSetAttribute(flash_attn, cudaFuncAttributeMaxDynamicSharedMemorySize, FA_SMEM);
        cudaStreamCreateWithFlags(&s1, cudaStreamNonBlocking);
        cudaStreamCreateWithFlags(&s2, cudaStreamNonBlocking);
        cudaEventCreateWithFlags(&e0, cudaEventDisableTiming);
        cudaEventCreateWithFlags(&e1, cudaEventDisableTiming);
        cudaEventCreateWithFlags(&e2, cudaEventDisableTiming);
        s_init = true;
    }

    const float* cur_raw  = (const float*)d_in[0];
    const float* ctx_raw  = (const float*)d_in[1];
    const float* pre_raw  = (const float*)d_in[2];
    const int*   ctx_mask = (const int*)d_in[3];
    const int*   utt_mask = (const int*)d_in[4];
    const float* norm_W   = (const float*)d_in[5];
    const float* norm_b   = (const float*)d_in[6];
    const float* norm_g   = (const float*)d_in[7];
    const float* norm_be  = (const float*)d_in[8];
    const float* Wq = (const float*)d_in[9];
    const float* bq = (const float*)d_in[10];
    const float* Wk = (const float*)d_in[11];
    const float* bk = (const float*)d_in[12];
    const float* Wv = (const float*)d_in[13];
    const float* bv = (const float*)d_in[14];
    const float* Wo = (const float*)d_in[15];
    const float* bo = (const float*)d_in[16];
    const float* ln_g = (const float*)d_in[17];
    const float* ln_b = (const float*)d_in[18];
    const float* W1 = (const float*)d_in[19];
    const float* b1 = (const float*)d_in[20];
    const float* W2 = (const float*)d_in[21];
    const float* b2 = (const float*)d_in[22];

    float* out  = (float*)d_out;
    float* cur_out   = out;
    float* slots_out = out + (long long)BB * LU * DD;

    float* fea_cur   = sym<float>(g_fea_cur);
    float* fea_ctx   = sym<float>(g_fea_ctx);
    float* fea_slots = sym<float>(g_fea_slots);
    float* cur_attn  = sym<float>(g_cur_attn);
    float* va = sym<float>(g_va);
    float* bkv0 = sym<float>(g_bkv0);
    float* bkv1 = sym<float>(g_bkv1);

    f16 *wn = sym<f16>(g_wn);
    f16 *wq = sym<f16>(g_wq);
    f16 *wkv0 = sym<f16>(g_wkv0);
    f16 *wkv1 = sym<f16>(g_wkv1);
    f16 *wo = sym<f16>(g_wo);
    f16 *w1 = sym<f16>(g_w1);
    f16 *w2 = sym<f16>(g_w2);
    f16 *xcur = sym<f16>(g_xcur);
    f16 *xctx = sym<f16>(g_xctx);
    f16 *xpre = sym<f16>(g_xpre);
    f16 *fc = sym<f16>(g_fc);
    f16 *fx = sym<f16>(g_fx);
    f16 *fs = sym<f16>(g_fs);
    f16 *lnb = sym<f16>(g_lnb);
    f16 *ffh = sym<f16>(g_ffh);
    f16 *a0 = sym<f16>(g_a0);
    f16 *a1 = sym<f16>(g_a1);
    f16 *co = sym<f16>(g_co);
    f16 *q0 = sym<f16>(g_q0);
    f16 *kv0 = sym<f16>(g_kv0);
    f16 *q1 = sym<f16>(g_q1);
    f16 *kv1 = sym<f16>(g_kv1);

    const int DxD = DD * DD;
    const int N2 = 2 * DD;

    // ---- packed biases (one kernel node)
    pack_bias<<<(DD + 255) / 256, 256>>>(bk, bv, bkv0, bkv1);

    // ---- one launch for ALL fp32->f16 conversions (with KV weight packing)
    {
        ConvArgs ca;
        const float* xs[NSEG] = { norm_W, Wq, Wo, W1, W2,
                                  Wk, Wv, Wk + DxD, Wv + DxD,
                                  cur_raw, ctx_raw, pre_raw };
        f16* hs[NSEG] = { wn, wq, wo, w1, w2,
                          wkv0, wkv0, wkv1, wkv1,
                          xcur, xctx, xpre };
        int ns[NSEG] = { 3*DxD/4, 2*DxD/4, 2*DxD/4, 2*DD*DFF/4, 2*DFF*DD/4,
                         DxD/4, DxD/4, DxD/4, DxD/4,
                         BB*LU*DD/4, BB*LC*DD/4, SS*BB*DD/4 };
        int ld4[NSEG] = { 192, 192, 192, 192, 192, 384, 384, 384, 384, 192, 192, 192 };
        int co4[NSEG] = { 0, 0, 0, 0, 0, 0, 192, 0, 192, 0, 0, 0 };
        for (int i = 0; i < NSEG; i++) {
            ca.x[i]=xs[i]; ca.h[i]=hs[i];
            ca.n4[i]=ns[i]; ca.ldo4[i]=ld4[i]; ca.coff4[i]=co4[i];
        }
        conv_multi<<<dim3(128, NSEG), 256>>>(ca);
    }
    cudaEventRecord(e0, 0);
    cudaStreamWaitEvent(s1, e0, 0);
    cudaStreamWaitEvent(s2, e0, 0);

    // ---- s1: cur chain (norm -> LN -> Q0)
    run_lin_s(s1, xcur, wn, fea_cur, BB * LU, DD, DD, norm_b, nullptr, 0);
    ln_warp<<<BB * LU / 8, 256, 0, s1>>>(fea_cur, fea_cur, fc, norm_g, norm_be);
    run_lin_s(s1, fc, wq, nullptr, BB * LU, DD, DD, bq, nullptr, 0, q0);
    cudaEventRecord(e1, s1);

    // ---- s2: slots chain (norm -> LN -> Q1)
    run_lin_s(s2, xpre, wn + 2 * DxD, fea_slots, SS * BB, DD, DD,
              norm_b + 2 * DD, nullptr, 0);
    ln_warp<<<SS * BB / 8, 256, 0, s2>>>(fea_slots, fea_slots, fs,
                                         norm_g + 2 * DD, norm_be + 2 * DD);
    run_lin_s(s2, fs, wq + DxD, nullptr, SS * BB, DD, DD, bq + DD, nullptr, 0, q1);
    cudaEventRecord(e2, s2);

    // ---- main: ctx chain (norm -> LN -> fused K0|V0)
    run_lin_s(0, xctx, wn + DxD, fea_ctx, BB * LC, DD, DD, norm_b + DD, nullptr, 0);
    ln_warp<<<BB * LC / 8, 256>>>(fea_ctx, nullptr, fx, norm_g + DD, norm_be + DD);
    run_lin_s(0, fx, wkv0, nullptr, BB * LC, N2, DD, bkv0, nullptr, 0, kv0);

    cudaStreamWaitEvent(0, e1, 0);

    // ---- stage B (main)
    flash_attn<<<BB * HH, 256, FA_SMEM>>>(q0, kv0, kv0 + DD, ctx_mask, a0,
                                          LU, LC, LU, 1, LU, N2, 0.125f);
    run_lin_s(0, a0, wo, cur_attn, BB * LU, DD, DD, bo, fea_cur, 0);
    ln_warp<<<BB * LU / 8, 256>>>(cur_attn, nullptr, lnb, ln_g, ln_b);
    run_lin_s(0, lnb, w1, nullptr, BB * LU, DFF, DD, b1, nullptr, 1, ffh);
    run_lin_s(0, ffh, w2, cur_out, BB * LU, DD, DFF, b2, cur_attn, 0, co);

    // ---- stage C (main): fused K1|V1
    run_lin_s(0, co, wkv1, nullptr, BB * LU, N2, DD, bkv1, nullptr, 0, kv1);

    cudaStreamWaitEvent(0, e2, 0);

    flash_attn<<<BB * HH, 256, FA_SMEM>>>(q1, kv1, kv1 + DD, utt_mask, a1,
                                          SS, LU, 1, BB, SS, N2, 0.125f);

    // Wo-proj with fused transpose-residual: va[S,B,D] = (a1@Wo + bo) + fea_slots
    run_lin_s(0, a1, wo + DxD, va, BB * SS, DD, DD, bo + DD, fea_slots, 0, nullptr, 1);

    ln_warp<<<SS * BB / 8, 256>>>(va, nullptr, lnb, ln_g + DD, ln_b + DD);
    run_lin_s(0, lnb, w1 + DD * DFF, nullptr, SS * BB, DFF, DD, b1 + DFF, nullptr, 1, ffh);
    run_lin_s(0, ffh, w2 + DFF * DD, slots_out, SS * BB, DD, DFF, b2 + DD, va, 0);
}

// round 16
// speedup vs baseline: 1.5308x; 1.0309x over previous
#include <cuda_runtime.h>
#include <cuda_fp16.h>
#include <cstdint>

// Problem dims
#define BB   32
#define LU   128
#define LC   512
#define SS   30
#define DD   768
#define HH   12
#define DK   64
#define DFF  1152

typedef __half  f16;
typedef __half2 f162;

// ---------------- fp32 scratch ----------------------------------------------
__device__ __align__(256) float g_fea_cur[BB*LU*DD];
__device__ __align__(256) float g_fea_ctx[BB*LC*DD];
__device__ __align__(256) float g_fea_slots[SS*BB*DD];
__device__ __align__(256) float g_cur_attn[BB*LU*DD];
__device__ __align__(256) float g_va[SS*BB*DD];
__device__ __align__(256) float g_bkv0[2*DD];
__device__ __align__(256) float g_bkv1[2*DD];

// ---------------- f16 scratch (single precision everywhere) -----------------
__device__ __align__(256) f16 g_wn[3*DD*DD];
__device__ __align__(256) f16 g_wq[2*DD*DD];
__device__ __align__(256) f16 g_wkv0[DD*2*DD];
__device__ __align__(256) f16 g_wkv1[DD*2*DD];
__device__ __align__(256) f16 g_wo[2*DD*DD];
__device__ __align__(256) f16 g_w1[2*DD*DFF];
__device__ __align__(256) f16 g_w2[2*DFF*DD];
__device__ __align__(256) f16 g_xcur[BB*LU*DD];
__device__ __align__(256) f16 g_xctx[BB*LC*DD];
__device__ __align__(256) f16 g_xpre[SS*BB*DD];
__device__ __align__(256) f16 g_fc[BB*LU*DD];
__device__ __align__(256) f16 g_fx[BB*LC*DD];
__device__ __align__(256) f16 g_fs[SS*BB*DD];
__device__ __align__(256) f16 g_lnb[BB*LU*DD];
__device__ __align__(256) f16 g_ffh[BB*LU*DFF];
__device__ __align__(256) f16 g_a0[BB*LU*DD];
__device__ __align__(256) f16 g_a1[BB*SS*DD];
__device__ __align__(256) f16 g_co[BB*LU*DD];
__device__ __align__(256) f16 g_q0[BB*LU*DD];
__device__ __align__(256) f16 g_kv0[BB*LC*2*DD];
__device__ __align__(256) f16 g_q1[SS*BB*DD];
__device__ __align__(256) f16 g_kv1[BB*LU*2*DD];

// =================== helpers ================================================
__device__ __forceinline__ uint32_t smem_u32(const void* p) {
    uint32_t a;
    asm("{ .reg .u64 t; cvta.to.shared.u64 t, %1; cvt.u32.u64 %0, t; }" : "=r"(a) : "l"(p));
    return a;
}
__device__ __forceinline__ void ldm_x4(uint32_t* r, uint32_t addr) {
    asm volatile("ldmatrix.sync.aligned.m8n8.x4.shared.b16 {%0,%1,%2,%3}, [%4];"
                 : "=r"(r[0]), "=r"(r[1]), "=r"(r[2]), "=r"(r[3]) : "r"(addr));
}
__device__ __forceinline__ void ldm_x4_t(uint32_t* r, uint32_t addr) {
    asm volatile("ldmatrix.sync.aligned.m8n8.x4.trans.shared.b16 {%0,%1,%2,%3}, [%4];"
                 : "=r"(r[0]), "=r"(r[1]), "=r"(r[2]), "=r"(r[3]) : "r"(addr));
}
__device__ __forceinline__ void mma_f16(float* c, const uint32_t* a, const uint32_t* b) {
    asm volatile("mma.sync.aligned.m16n8k16.row.col.f32.f16.f16.f32 "
                 "{%0,%1,%2,%3}, {%4,%5,%6,%7}, {%8,%9}, {%0,%1,%2,%3};"
                 : "+f"(c[0]), "+f"(c[1]), "+f"(c[2]), "+f"(c[3])
                 : "r"(a[0]), "r"(a[1]), "r"(a[2]), "r"(a[3]), "r"(b[0]), "r"(b[1]));
}
__device__ __forceinline__ void mma_f16_b(float* c, const uint32_t* a, uint32_t b0, uint32_t b1) {
    asm volatile("mma.sync.aligned.m16n8k16.row.col.f32.f16.f16.f32 "
                 "{%0,%1,%2,%3}, {%4,%5,%6,%7}, {%8,%9}, {%0,%1,%2,%3};"
                 : "+f"(c[0]), "+f"(c[1]), "+f"(c[2]), "+f"(c[3])
                 : "r"(a[0]), "r"(a[1]), "r"(a[2]), "r"(a[3]), "r"(b0), "r"(b1));
}
__device__ __forceinline__ void split2h(float x, float y, f162& h, f162& l) {
    f16 hx = __float2half_rn(x), hy = __float2half_rn(y);
    h = __halves2half2(hx, hy);
    l = __halves2half2(__float2half_rn(x - __half2float(hx)),
                       __float2half_rn(y - __half2float(hy)));
}

// --------- merged fp32 -> f16 converter, with column packing ----------------
#define NSEGMAX 8
struct ConvArgs {
    const float* x[NSEGMAX];
    f16* h[NSEGMAX];
    int n4[NSEGMAX];
    int ldo4[NSEGMAX];
    int coff4[NSEGMAX];
};
__global__ __launch_bounds__(256)
void conv_multi(ConvArgs a)
{
    int s = blockIdx.y;
    int n4 = a.n4[s];
    const float* x = a.x[s];
    f16* h = a.h[s];
    int ldo4 = a.ldo4[s], coff4 = a.coff4[s];
    int stride = gridDim.x * 256;
    for (int i = blockIdx.x * 256 + threadIdx.x; i < n4; i += stride) {
        float4 v = ((const float4*)x)[i];
        f162 h01 = __halves2half2(__float2half_rn(v.x), __float2half_rn(v.y));
        f162 h23 = __halves2half2(__float2half_rn(v.z), __float2half_rn(v.w));
        int o4 = (i / 192) * ldo4 + coff4 + (i % 192);
        ((f162*)h)[2*o4]   = h01;
        ((f162*)h)[2*o4+1] = h23;
    }
}

// ------------- pack KV biases in one kernel ---------------------------------
__global__ __launch_bounds__(256)
void pack_bias(const float* __restrict__ bk, const float* __restrict__ bv,
               float* __restrict__ bkv0, float* __restrict__ bkv1)
{
    int i = blockIdx.x * 256 + threadIdx.x;
    if (i >= DD) return;
    bkv0[i]      = bk[i];
    bkv0[DD + i] = bv[i];
    bkv1[i]      = bk[DD + i];
    bkv1[DD + i] = bv[DD + i];
}

// ========= single-f16 HMMA GEMM, KC=32, 2-stage cp.async ====================
#define A_STRIDE 80
#define B_STRIDE 272
#define KC 32
#define B_TILE 8704            // 32 * 272

template<int MT>
__device__ __forceinline__ void stage_load(
    uint32_t stg, const f16* __restrict__ A, const f16* __restrict__ B,
    int m0, int n0, int kc0, int M, int N, int K, int tid)
{
    constexpr int SA = MT * A_STRIDE;
    #pragma unroll
    for (int i = 0; i < MT / 64; i++) {
        int ca = tid + (i << 8);
        int r = ca >> 2, seg = ca & 3;
        int m = m0 + r;
        uint32_t dst = stg + (uint32_t)(r * A_STRIDE + seg * 16);
        int sz = (m < M) ? 16 : 0;
        size_t so = (size_t)m * K + kc0 + seg * 8;
        asm volatile("cp.async.cg.shared.global [%0], [%1], 16, %2;"
                     :: "r"(dst), "l"(A + so), "r"(sz));
    }
    #pragma unroll
    for (int i = 0; i < 2; i++) {
        int cb = tid + (i << 8);
        int r = cb >> 4, seg = cb & 15;
        uint32_t dst = stg + (uint32_t)(SA + r * B_STRIDE + seg * 16);
        size_t so = (size_t)(kc0 + r) * N + n0 + seg * 8;
        asm volatile("cp.async.cg.shared.global [%0], [%1], 16;"
                     :: "r"(dst), "l"(B + so));
    }
    asm volatile("cp.async.commit_group;");
}

template<int MT>
__global__ void __launch_bounds__(256, 3)
mma_gemm(const f16* __restrict__ A, const f16* __restrict__ B,
         float* __restrict__ C, int M, int N, int K,
         const float* __restrict__ bias, const float* __restrict__ res, int relu,
         f16* __restrict__ Ch, int trans)
{
    constexpr int SA  = MT * A_STRIDE;
    constexpr int TSTG = SA + B_TILE;
    constexpr int WM = (MT == 128) ? 4 : 2;
    constexpr int NP = (MT == 128) ? 4 : 2;

    extern __shared__ __align__(128) char smem[];
    const uint32_t sb = smem_u32(smem);
    const int tid = threadIdx.x;
    const int wid = tid >> 5, lane = tid & 31;
    const int m0 = blockIdx.y * MT, n0 = blockIdx.x * 128;
    const int mw = (wid % WM) * 32;
    const int nw = (wid / WM) * (NP * 16);

    float acc[2][NP * 2][4];
    #pragma unroll
    for (int i = 0; i < 2; i++)
        #pragma unroll
        for (int j = 0; j < NP * 2; j++)
            #pragma unroll
            for (int q = 0; q < 4; q++) acc[i][j][q] = 0.f;

    const int lsub = lane >> 3, lr = lane & 7;
    const uint32_t aOff = (uint32_t)((lr + (lsub & 1) * 8) * A_STRIDE + (lsub >> 1) * 16);
    const uint32_t bOff = (uint32_t)((lr + (lsub & 1) * 8) * B_STRIDE + (lsub >> 1) * 16);

    const int nc = K / KC;
    stage_load<MT>(sb, A, B, m0, n0, 0, M, N, K, tid);

    for (int c = 0; c < nc; c++) {
        if (c + 1 < nc) {
            stage_load<MT>(sb + ((c + 1) & 1) * TSTG, A, B,
                           m0, n0, (c + 1) * KC, M, N, K, tid);
            asm volatile("cp.async.wait_group 1;");
        } else {
            asm volatile("cp.async.wait_group 0;");
        }
        __syncthreads();

        const uint32_t st = sb + (c & 1) * TSTG;
        #pragma unroll
        for (int ks = 0; ks < KC; ks += 16) {
            uint32_t ah[2][4];
            #pragma unroll
            for (int mi = 0; mi < 2; mi++) {
                uint32_t off = aOff + (uint32_t)((mw + mi * 16) * A_STRIDE + ks * 2);
                ldm_x4(ah[mi], st + off);
            }
            #pragma unroll
            for (int np = 0; np < NP; np++) {
                uint32_t off = bOff + (uint32_t)(ks * B_STRIDE + (nw + np * 16) * 2);
                uint32_t bh[4];
                ldm_x4_t(bh, st + SA + off);
                #pragma unroll
                for (int mi = 0; mi < 2; mi++)
                    #pragma unroll
                    for (int g2 = 0; g2 < 2; g2++)
                        mma_f16(acc[mi][np * 2 + g2], ah[mi], bh + g2 * 2);
            }
        }
        __syncthreads();
    }

    // ---- epilogue
    const int qrow = lane >> 2, qcol = (lane & 3) * 2;
    #pragma unroll
    for (int mi = 0; mi < 2; mi++) {
        int r0 = m0 + mw + mi * 16 + qrow;
        #pragma unroll
        for (int ni = 0; ni < NP * 2; ni++) {
            int cidx = n0 + nw + ni * 8 + qcol;
            float* a = acc[mi][ni];
            #pragma unroll
            for (int hh = 0; hh < 2; hh++) {
                int r = r0 + hh * 8;
                if (r >= M) continue;
                int ro = trans ? ((r % SS) * BB + r / SS) : r;
                float x = a[hh * 2 + 0] + bias[cidx];
                float y = a[hh * 2 + 1] + bias[cidx + 1];
                if (relu) { x = fmaxf(x, 0.f); y = fmaxf(y, 0.f); }
                if (res) {
                    const float2 rv = *(const float2*)&res[(size_t)ro * N + cidx];
                    x += rv.x; y += rv.y;
                }
                if (C) {
                    float2 o; o.x = x; o.y = y;
                    *(float2*)&C[(size_t)ro * N + cidx] = o;
                }
                if (Ch) {
                    *(f162*)&Ch[(size_t)ro * N + cidx] =
                        __halves2half2(__float2half_rn(x), __float2half_rn(y));
                }
            }
        }
    }
}

#define STG128 (128 * A_STRIDE + B_TILE)
#define STG64  (64  * A_STRIDE + B_TILE)

// ====== fused flash attention: q-tile 64, 128 threads, 3 CTAs/SM ============
#define FA_STRIDE 144
#define FA_K 0
#define FA_V 18432
#define FA_MASK 36864
#define FA_SMEM (FA_MASK + 512)

__global__ void __launch_bounds__(128, 3)
flash_attn(const f16* __restrict__ Q, const f16* __restrict__ K,
           const f16* __restrict__ V, const int* __restrict__ mask,
           f16* __restrict__ O,
           int Lq, int Lk, int qB, int qS, int oB, int kvld, float scale)
{
    extern __shared__ __align__(128) char smem[];
    const uint32_t sb = smem_u32(smem);
    const float* sbias = (const float*)(smem + FA_MASK);
    const int tid = threadIdx.x, wid = tid >> 5, lane = tid & 31;
    const int z = blockIdx.x, b = z / HH, h = z % HH;
    const int qb0 = blockIdx.y * 64;
    const int qt = lane >> 2, qc = (lane & 3) * 2;
    const int r0 = qb0 + wid * 16 + qt, r1 = r0 + 8;
    const int colh = h * DK;

    uint32_t qf[4][4];
    #pragma unroll
    for (int ks = 0; ks < 4; ks++) {
        #pragma unroll
        for (int p = 0; p < 4; p++) {
            int rr = (p & 1) ? r1 : r0;
            int kk = ks * 16 + qc + ((p >> 1) ? 8 : 0);
            if (rr < Lq) {
                size_t off = (size_t)(b * qB + rr * qS) * DD + colh + kk;
                qf[ks][p] = *(const uint32_t*)(Q + off);
            } else qf[ks][p] = 0u;
        }
    }

    float m0 = -1e30f, m1 = -1e30f, l0 = 0.f, l1 = 0.f;
    float oacc[8][4];
    #pragma unroll
    for (int j = 0; j < 8; j++)
        #pragma unroll
        for (int q = 0; q < 4; q++) oacc[j][q] = 0.f;

    const uint32_t ldOffK = (uint32_t)(((lane & 7) + ((lane >> 3) & 1) * 8) * FA_STRIDE
                                       + ((lane >> 4) * 8) * 2);

    const int nch = Lk / 128;
    for (int ch = 0; ch < nch; ch++) {
        const int k0g = ch * 128;
        #pragma unroll
        for (int i = 0; i < 8; i++) {
            int idx = tid + (i << 7);
            int r = idx >> 3, seg = idx & 7;
            size_t src = (size_t)(b * Lk + k0g + r) * kvld + colh + seg * 8;
            uint32_t dst = sb + (uint32_t)(r * FA_STRIDE + seg * 16);
            asm volatile("cp.async.cg.shared.global [%0], [%1], 16;" :: "r"(dst + FA_K), "l"(K + src));
            asm volatile("cp.async.cg.shared.global [%0], [%1], 16;" :: "r"(dst + FA_V), "l"(V + src));
        }
        asm volatile("cp.async.commit_group;");
        ((float*)(smem + FA_MASK))[tid] = mask[b * Lk + k0g + tid] ? 0.f : -1e9f;
        asm volatile("cp.async.wait_group 0;");
        __syncthreads();

        float sacc[16][4];
        #pragma unroll
        for (int j = 0; j < 16; j++)
            #pragma unroll
            for (int q = 0; q < 4; q++) sacc[j][q] = 0.f;

        #pragma unroll
        for (int ks = 0; ks < 4; ks++) {
            #pragma unroll
            for (int nt = 0; nt < 8; nt++) {
                uint32_t off = ldOffK + (uint32_t)(nt * 16 * FA_STRIDE + ks * 32);
                uint32_t kh4[4];
                ldm_x4(kh4, sb + FA_K + off);
                #pragma unroll
                for (int sub = 0; sub < 2; sub++)
                    mma_f16_b(sacc[nt * 2 + sub], qf[ks], kh4[sub], kh4[sub + 2]);
            }
        }

        float cm0 = -1e30f, cm1 = -1e30f;
        #pragma unroll
        for (int j = 0; j < 16; j++) {
            int kb = j * 8 + qc;
            float b0v = sbias[kb], b1v = sbias[kb + 1];
            sacc[j][0] = sacc[j][0] * scale + b0v;
            sacc[j][1] = sacc[j][1] * scale + b1v;
            sacc[j][2] = sacc[j][2] * scale + b0v;
            sacc[j][3] = sacc[j][3] * scale + b1v;
            cm0 = fmaxf(cm0, fmaxf(sacc[j][0], sacc[j][1]));
            cm1 = fmaxf(cm1, fmaxf(sacc[j][2], sacc[j][3]));
        }
        cm0 = fmaxf(cm0, __shfl_xor_sync(0xFFFFFFFFu, cm0, 1));
        cm0 = fmaxf(cm0, __shfl_xor_sync(0xFFFFFFFFu, cm0, 2));
        cm1 = fmaxf(cm1, __shfl_xor_sync(0xFFFFFFFFu, cm1, 1));
        cm1 = fmaxf(cm1, __shfl_xor_sync(0xFFFFFFFFu, cm1, 2));
        float nm0 = fmaxf(m0, cm0), nm1 = fmaxf(m1, cm1);
        float al0 = __expf(m0 - nm0), al1 = __expf(m1 - nm1);
        m0 = nm0; m1 = nm1;

        float ps0 = 0.f, ps1 = 0.f;
        #pragma unroll
        for (int j = 0; j < 16; j++) {
            float p0 = __expf(sacc[j][0] - nm0), p1 = __expf(sacc[j][1] - nm0);
            float p2 = __expf(sacc[j][2] - nm1), p3 = __expf(sacc[j][3] - nm1);
            ps0 += p0 + p1; ps1 += p2 + p3;
            sacc[j][0] = p0; sacc[j][1] = p1; sacc[j][2] = p2; sacc[j][3] = p3;
        }
        ps0 += __shfl_xor_sync(0xFFFFFFFFu, ps0, 1);
        ps0 += __shfl_xor_sync(0xFFFFFFFFu, ps0, 2);
        ps1 += __shfl_xor_sync(0xFFFFFFFFu, ps1, 1);
        ps1 += __shfl_xor_sync(0xFFFFFFFFu, ps1, 2);
        l0 = l0 * al0 + ps0; l1 = l1 * al1 + ps1;
        #pragma unroll
        for (int j = 0; j < 8; j++) {
            oacc[j][0] *= al0; oacc[j][1] *= al0;
            oacc[j][2] *= al1; oacc[j][3] *= al1;
        }

        #pragma unroll
        for (int kk = 0; kk < 8; kk++) {
            uint32_t ahp[4], alp[4];
            #pragma unroll
            for (int jj = 0; jj < 2; jj++) {
                const float* sp = sacc[2 * kk + jj];
                f162 h01, l01, h23, l23;
                split2h(sp[0], sp[1], h01, l01);
                split2h(sp[2], sp[3], h23, l23);
                ahp[jj * 2 + 0] = *(uint32_t*)&h01; ahp[jj * 2 + 1] = *(uint32_t*)&h23;
                alp[jj * 2 + 0] = *(uint32_t*)&l01; alp[jj * 2 + 1] = *(uint32_t*)&l23;
            }
            #pragma unroll
            for (int dt = 0; dt < 4; dt++) {
                uint32_t off = ldOffK + (uint32_t)(kk * 16 * FA_STRIDE + dt * 32);
                uint32_t vh4[4];
                ldm_x4_t(vh4, sb + FA_V + off);
                #pragma unroll
                for (int sub = 0; sub < 2; sub++)
                    mma_f16_b(oacc[dt * 2 + sub], ahp, vh4[sub*2], vh4[sub*2+1]);
                #pragma unroll
                for (int sub = 0; sub < 2; sub++)
                    mma_f16_b(oacc[dt * 2 + sub], alp, vh4[sub*2], vh4[sub*2+1]);
            }
        }
        __syncthreads();
    }

    float inv0 = 1.f / l0, inv1 = 1.f / l1;
    #pragma unroll
    for (int j = 0; j < 8; j++) {
        int col = colh + j * 8 + qc;
        if (r0 < Lq) {
            size_t off = (size_t)(b * oB + r0) * DD + col;
            *(f162*)(O + off) = __halves2half2(__float2half_rn(oacc[j][0] * inv0),
                                               __float2half_rn(oacc[j][1] * inv0));
        }
        if (r1 < Lq) {
            size_t off = (size_t)(b * oB + r1) * DD + col;
            *(f162*)(O + off) = __halves2half2(__float2half_rn(oacc[j][2] * inv1),
                                               __float2half_rn(oacc[j][3] * inv1));
        }
    }
}

// ------- LayerNorm: warp per row, single pass, register resident ------------
__global__ __launch_bounds__(256)
void ln_warp(const float* __restrict__ x, float* __restrict__ y,
             f16* __restrict__ yh,
             const float* __restrict__ g, const float* __restrict__ be)
{
    const int lane = threadIdx.x & 31;
    const size_t row = (size_t)(blockIdx.x * 8) + (threadIdx.x >> 5);
    const float* xr = x + row * DD;

    float4 v[6];
    float s = 0.f, s2 = 0.f;
    #pragma unroll
    for (int i = 0; i < 6; i++) {
        v[i] = *(const float4*)&xr[i * 128 + lane * 4];
        s  += v[i].x + v[i].y + v[i].z + v[i].w;
        s2 += v[i].x * v[i].x + v[i].y * v[i].y + v[i].z * v[i].z + v[i].w * v[i].w;
    }
    #pragma unroll
    for (int o = 16; o > 0; o >>= 1) {
        s  += __shfl_xor_sync(0xFFFFFFFFu, s, o);
        s2 += __shfl_xor_sync(0xFFFFFFFFu, s2, o);
    }
    const float mean = s * (1.f / DD);
    const float var  = s2 * (1.f / DD) - mean * mean;
    const float rstd = rsqrtf(var + 1e-5f);

    #pragma unroll
    for (int i = 0; i < 6; i++) {
        int col = i * 128 + lane * 4;
        float4 gv = *(const float4*)&g[col];
        float4 bv = *(const float4*)&be[col];
        float4 o;
        o.x = (v[i].x - mean) * rstd * gv.x + bv.x;
        o.y = (v[i].y - mean) * rstd * gv.y + bv.y;
        o.z = (v[i].z - mean) * rstd * gv.z + bv.z;
        o.w = (v[i].w - mean) * rstd * gv.w + bv.w;
        if (y) *(float4*)&y[row * DD + col] = o;
        if (yh) {
            *(f162*)&yh[row * DD + col] =
                __halves2half2(__float2half_rn(o.x), __float2half_rn(o.y));
            *(f162*)&yh[row * DD + col + 2] =
                __halves2half2(__float2half_rn(o.z), __float2half_rn(o.w));
        }
    }
}

// ---------------- host-side helpers ----------------------------------------
template<typename T>
static T* sym(const void* s) { void* p = nullptr; cudaGetSymbolAddress(&p, s); return (T*)p; }

static void run_lin_s(cudaStream_t st, const f16* A, const f16* W,
                      float* C, int M, int N, int K,
                      const float* bias, const float* res, int relu,
                      f16* Ch = nullptr, int trans = 0)
{
    int ctas128 = (N / 128) * ((M + 127) / 128);
    if (M <= 4096 && ctas128 < 232) {
        dim3 grid(N / 128, (M + 63) / 64);
        mma_gemm<64><<<grid, 256, 2 * STG64, st>>>(A, W, C, M, N, K, bias, res, relu, Ch, trans);
    } else {
        dim3 grid(N / 128, (M + 127) / 128);
        mma_gemm<128><<<grid, 256, 2 * STG128, st>>>(A, W, C, M, N, K, bias, res, relu, Ch, trans);
    }
}

extern "C" void kernel_launch(void* const* d_in, const int* in_sizes, int n_in,
                              void* d_out, int out_size)
{
    static bool s_init = false;
    static cudaStream_t s1, s2;
    static cudaEvent_t eS, e0, e1, e2, eW;
    if (!s_init) {
        cudaFuncSetAttribute(mma_gemm<128>, cudaFuncAttributeMaxDynamicSharedMemorySize, 2 * STG128);
        cudaFuncSetAttribute(mma_gemm<64>,  cudaFuncAttributeMaxDynamicSharedMemorySize, 2 * STG64);
        cudaFuncSetAttribute(flash_attn, cudaFuncAttributeMaxDynamicSharedMemorySize, FA_SMEM);
        cudaStreamCreateWithFlags(&s1, cudaStreamNonBlocking);
        cudaStreamCreateWithFlags(&s2, cudaStreamNonBlocking);
        cudaEventCreateWithFlags(&eS, cudaEventDisableTiming);
        cudaEventCreateWithFlags(&e0, cudaEventDisableTiming);
        cudaEventCreateWithFlags(&e1, cudaEventDisableTiming);
        cudaEventCreateWithFlags(&e2, cudaEventDisableTiming);
        cudaEventCreateWithFlags(&eW, cudaEventDisableTiming);
        s_init = true;
    }

    const float* cur_raw  = (const float*)d_in[0];
    const float* ctx_raw  = (const float*)d_in[1];
    const float* pre_raw  = (const float*)d_in[2];
    const int*   ctx_mask = (const int*)d_in[3];
    const int*   utt_mask = (const int*)d_in[4];
    const float* norm_W   = (const float*)d_in[5];
    const float* norm_b   = (const float*)d_in[6];
    const float* norm_g   = (const float*)d_in[7];
    const float* norm_be  = (const float*)d_in[8];
    const float* Wq = (const float*)d_in[9];
    const float* bq = (const float*)d_in[10];
    const float* Wk = (const float*)d_in[11];
    const float* bk = (const float*)d_in[12];
    const float* Wv = (const float*)d_in[13];
    const float* bv = (const float*)d_in[14];
    const float* Wo = (const float*)d_in[15];
    const float* bo = (const float*)d_in[16];
    const float* ln_g = (const float*)d_in[17];
    const float* ln_b = (const float*)d_in[18];
    const float* W1 = (const float*)d_in[19];
    const float* b1 = (const float*)d_in[20];
    const float* W2 = (const float*)d_in[21];
    const float* b2 = (const float*)d_in[22];

    float* out  = (float*)d_out;
    float* cur_out   = out;
    float* slots_out = out + (long long)BB * LU * DD;

    float* fea_cur   = sym<float>(g_fea_cur);
    float* fea_ctx   = sym<float>(g_fea_ctx);
    float* fea_slots = sym<float>(g_fea_slots);
    float* cur_attn  = sym<float>(g_cur_attn);
    float* va = sym<float>(g_va);
    float* bkv0 = sym<float>(g_bkv0);
    float* bkv1 = sym<float>(g_bkv1);

    f16 *wn = sym<f16>(g_wn);
    f16 *wq = sym<f16>(g_wq);
    f16 *wkv0 = sym<f16>(g_wkv0);
    f16 *wkv1 = sym<f16>(g_wkv1);
    f16 *wo = sym<f16>(g_wo);
    f16 *w1 = sym<f16>(g_w1);
    f16 *w2 = sym<f16>(g_w2);
    f16 *xcur = sym<f16>(g_xcur);
    f16 *xctx = sym<f16>(g_xctx);
    f16 *xpre = sym<f16>(g_xpre);
    f16 *fc = sym<f16>(g_fc);
    f16 *fx = sym<f16>(g_fx);
    f16 *fs = sym<f16>(g_fs);
    f16 *lnb = sym<f16>(g_lnb);
    f16 *ffh = sym<f16>(g_ffh);
    f16 *a0 = sym<f16>(g_a0);
    f16 *a1 = sym<f16>(g_a1);
    f16 *co = sym<f16>(g_co);
    f16 *q0 = sym<f16>(g_q0);
    f16 *kv0 = sym<f16>(g_kv0);
    f16 *q1 = sym<f16>(g_q1);
    f16 *kv1 = sym<f16>(g_kv1);

    const int DxD = DD * DD;
    const int N2 = 2 * DD;

    // ---- fork point: everything below hangs off the main stream
    pack_bias<<<(DD + 255) / 256, 256>>>(bk, bv, bkv0, bkv1);
    cudaEventRecord(eS, 0);

    // ---- s1 joins capture, then runs conv group B (weights) concurrently
    cudaStreamWaitEvent(s1, eS, 0);
    {
        ConvArgs ca;
        const float* xs[8] = { Wq, Wo, W1, W2, Wk, Wv, Wk + DxD, Wv + DxD };
        f16* hs[8] = { wq, wo, w1, w2, wkv0, wkv0, wkv1, wkv1 };
        int ns[8] = { 2*DxD/4, 2*DxD/4, 2*DD*DFF/4, 2*DFF*DD/4,
                      DxD/4, DxD/4, DxD/4, DxD/4 };
        int ld4[8] = { 192, 192, 192, 192, 384, 384, 384, 384 };
        int co4[8] = { 0, 0, 0, 0, 0, 192, 0, 192 };
        for (int i = 0; i < 8; i++) {
            ca.x[i]=xs[i]; ca.h[i]=hs[i]; ca.n4[i]=ns[i];
            ca.ldo4[i]=ld4[i]; ca.coff4[i]=co4[i];
        }
        conv_multi<<<dim3(96, 8), 256, 0, s1>>>(ca);
    }
    cudaEventRecord(eW, s1);

    // ---- conv group A (inputs + norm weights) on main
    {
        ConvArgs ca;
        const float* xs[4] = { norm_W, cur_raw, ctx_raw, pre_raw };
        f16* hs[4] = { wn, xcur, xctx, xpre };
        int ns[4] = { 3*DxD/4, BB*LU*DD/4, BB*LC*DD/4, SS*BB*DD/4 };
        for (int i = 0; i < 4; i++) {
            ca.x[i]=xs[i]; ca.h[i]=hs[i]; ca.n4[i]=ns[i];
            ca.ldo4[i]=192; ca.coff4[i]=0;
        }
        conv_multi<<<dim3(160, 4), 256>>>(ca);
    }
    cudaEventRecord(e0, 0);

    // ---- s1: cur chain (needs conv A for xcur/wn; wq from its own conv B)
    cudaStreamWaitEvent(s1, e0, 0);
    run_lin_s(s1, xcur, wn, fea_cur, BB * LU, DD, DD, norm_b, nullptr, 0);
    ln_warp<<<BB * LU / 8, 256, 0, s1>>>(fea_cur, fea_cur, fc, norm_g, norm_be);
    run_lin_s(s1, fc, wq, nullptr, BB * LU, DD, DD, bq, nullptr, 0, q0);
    cudaEventRecord(e1, s1);

    // ---- s2: slots chain (needs conv A + wq from conv B)
    cudaStreamWaitEvent(s2, e0, 0);
    cudaStreamWaitEvent(s2, eW, 0);
    run_lin_s(s2, xpre, wn + 2 * DxD, fea_slots, SS * BB, DD, DD,
              norm_b + 2 * DD, nullptr, 0);
    ln_warp<<<SS * BB / 8, 256, 0, s2>>>(fea_slots, fea_slots, fs,
                                         norm_g + 2 * DD, norm_be + 2 * DD);
    run_lin_s(s2, fs, wq + DxD, nullptr, SS * BB, DD, DD, bq + DD, nullptr, 0, q1);
    cudaEventRecord(e2, s2);

    // ---- main: ctx chain (norm -> LN -> fused K0|V0)
    run_lin_s(0, xctx, wn + DxD, fea_ctx, BB * LC, DD, DD, norm_b + DD, nullptr, 0);
    ln_warp<<<BB * LC / 8, 256>>>(fea_ctx, nullptr, fx, norm_g + DD, norm_be + DD);
    cudaStreamWaitEvent(0, eW, 0);
    run_lin_s(0, fx, wkv0, nullptr, BB * LC, N2, DD, bkv0, nullptr, 0, kv0);

    cudaStreamWaitEvent(0, e1, 0);

    // ---- stage B (main)
    flash_attn<<<dim3(BB * HH, 2), 128, FA_SMEM>>>(q0, kv0, kv0 + DD, ctx_mask, a0,
                                                   LU, LC, LU, 1, LU, N2, 0.125f);
    run_lin_s(0, a0, wo, cur_attn, BB * LU, DD, DD, bo, fea_cur, 0);
    ln_warp<<<BB * LU / 8, 256>>>(cur_attn, nullptr, lnb, ln_g, ln_b);
    run_lin_s(0, lnb, w1, nullptr, BB * LU, DFF, DD, b1, nullptr, 1, ffh);
    run_lin_s(0, ffh, w2, cur_out, BB * LU, DD, DFF, b2, cur_attn, 0, co);

    // ---- stage C (main): fused K1|V1
    run_lin_s(0, co, wkv1, nullptr, BB * LU, N2, DD, bkv1, nullptr, 0, kv1);

    cudaStreamWaitEvent(0, e2, 0);

    flash_attn<<<dim3(BB * HH, 1), 128, FA_SMEM>>>(q1, kv1, kv1 + DD, utt_mask, a1,
                                                   SS, LU, 1, BB, SS, N2, 0.125f);

    // Wo-proj with fused transpose-residual: va[S,B,D] = (a1@Wo + bo) + fea_slots
    run_lin_s(0, a1, wo + DxD, va, BB * SS, DD, DD, bo + DD, fea_slots, 0, nullptr, 1);

    ln_warp<<<SS * BB / 8, 256>>>(va, nullptr, lnb, ln_g + DD, ln_b + DD);
    run_lin_s(0, lnb, w1 + DD * DFF, nullptr, SS * BB, DFF, DD, b1 + DFF, nullptr, 1, ffh);
    run_lin_s(0, ffh, w2 + DFF * DD, slots_out, SS * BB, DD, DFF, b2 + DD, va, 0);
}

// round 17
// speedup vs baseline: 1.5379x; 1.0046x over previous
#include <cuda_runtime.h>
#include <cuda_fp16.h>
#include <cstdint>

// Problem dims
#define BB   32
#define LU   128
#define LC   512
#define SS   30
#define DD   768
#define HH   12
#define DK   64
#define DFF  1152

typedef __half  f16;
typedef __half2 f162;

// ---------------- fp32 scratch ----------------------------------------------
__device__ __align__(256) float g_fea_cur[BB*LU*DD];
__device__ __align__(256) float g_fea_ctx[BB*LC*DD];
__device__ __align__(256) float g_fea_slots[SS*BB*DD];
__device__ __align__(256) float g_cur_attn[BB*LU*DD];
__device__ __align__(256) float g_va[SS*BB*DD];
__device__ __align__(256) float g_bkv0[2*DD];
__device__ __align__(256) float g_bkv1[2*DD];

// ---------------- f16 scratch (single precision everywhere) -----------------
__device__ __align__(256) f16 g_wn[3*DD*DD];
__device__ __align__(256) f16 g_wq[2*DD*DD];
__device__ __align__(256) f16 g_wkv0[DD*2*DD];
__device__ __align__(256) f16 g_wkv1[DD*2*DD];
__device__ __align__(256) f16 g_wo[2*DD*DD];
__device__ __align__(256) f16 g_w1[2*DD*DFF];
__device__ __align__(256) f16 g_w2[2*DFF*DD];
__device__ __align__(256) f16 g_xcur[BB*LU*DD];
__device__ __align__(256) f16 g_xctx[BB*LC*DD];
__device__ __align__(256) f16 g_xpre[SS*BB*DD];
__device__ __align__(256) f16 g_fc[BB*LU*DD];
__device__ __align__(256) f16 g_fx[BB*LC*DD];
__device__ __align__(256) f16 g_fs[SS*BB*DD];
__device__ __align__(256) f16 g_lnb[BB*LU*DD];
__device__ __align__(256) f16 g_ffh[BB*LU*DFF];
__device__ __align__(256) f16 g_a0[BB*LU*DD];
__device__ __align__(256) f16 g_a1[BB*SS*DD];
__device__ __align__(256) f16 g_co[BB*LU*DD];
__device__ __align__(256) f16 g_q0[BB*LU*DD];
__device__ __align__(256) f16 g_kv0[BB*LC*2*DD];
__device__ __align__(256) f16 g_q1[SS*BB*DD];
__device__ __align__(256) f16 g_kv1[BB*LU*2*DD];

// =================== helpers ================================================
__device__ __forceinline__ uint32_t smem_u32(const void* p) {
    uint32_t a;
    asm("{ .reg .u64 t; cvta.to.shared.u64 t, %1; cvt.u32.u64 %0, t; }" : "=r"(a) : "l"(p));
    return a;
}
__device__ __forceinline__ void ldm_x4(uint32_t* r, uint32_t addr) {
    asm volatile("ldmatrix.sync.aligned.m8n8.x4.shared.b16 {%0,%1,%2,%3}, [%4];"
                 : "=r"(r[0]), "=r"(r[1]), "=r"(r[2]), "=r"(r[3]) : "r"(addr));
}
__device__ __forceinline__ void ldm_x4_t(uint32_t* r, uint32_t addr) {
    asm volatile("ldmatrix.sync.aligned.m8n8.x4.trans.shared.b16 {%0,%1,%2,%3}, [%4];"
                 : "=r"(r[0]), "=r"(r[1]), "=r"(r[2]), "=r"(r[3]) : "r"(addr));
}
__device__ __forceinline__ void mma_f16(float* c, const uint32_t* a, const uint32_t* b) {
    asm volatile("mma.sync.aligned.m16n8k16.row.col.f32.f16.f16.f32 "
                 "{%0,%1,%2,%3}, {%4,%5,%6,%7}, {%8,%9}, {%0,%1,%2,%3};"
                 : "+f"(c[0]), "+f"(c[1]), "+f"(c[2]), "+f"(c[3])
                 : "r"(a[0]), "r"(a[1]), "r"(a[2]), "r"(a[3]), "r"(b[0]), "r"(b[1]));
}
__device__ __forceinline__ void mma_f16_b(float* c, const uint32_t* a, uint32_t b0, uint32_t b1) {
    asm volatile("mma.sync.aligned.m16n8k16.row.col.f32.f16.f16.f32 "
                 "{%0,%1,%2,%3}, {%4,%5,%6,%7}, {%8,%9}, {%0,%1,%2,%3};"
                 : "+f"(c[0]), "+f"(c[1]), "+f"(c[2]), "+f"(c[3])
                 : "r"(a[0]), "r"(a[1]), "r"(a[2]), "r"(a[3]), "r"(b0), "r"(b1));
}
__device__ __forceinline__ void split2h(float x, float y, f162& h, f162& l) {
    f16 hx = __float2half_rn(x), hy = __float2half_rn(y);
    h = __halves2half2(hx, hy);
    l = __halves2half2(__float2half_rn(x - __half2float(hx)),
                       __float2half_rn(y - __half2float(hy)));
}

// --------- merged fp32 -> f16 converter, with column packing ----------------
#define NSEGMAX 8
struct ConvArgs {
    const float* x[NSEGMAX];
    f16* h[NSEGMAX];
    int n4[NSEGMAX];
    int ldo4[NSEGMAX];
    int coff4[NSEGMAX];
};
__global__ __launch_bounds__(256)
void conv_multi(ConvArgs a)
{
    int s = blockIdx.y;
    int n4 = a.n4[s];
    const float* x = a.x[s];
    f16* h = a.h[s];
    int ldo4 = a.ldo4[s], coff4 = a.coff4[s];
    int stride = gridDim.x * 256;
    for (int i = blockIdx.x * 256 + threadIdx.x; i < n4; i += stride) {
        float4 v = ((const float4*)x)[i];
        f162 h01 = __halves2half2(__float2half_rn(v.x), __float2half_rn(v.y));
        f162 h23 = __halves2half2(__float2half_rn(v.z), __float2half_rn(v.w));
        int o4 = (i / 192) * ldo4 + coff4 + (i % 192);
        ((f162*)h)[2*o4]   = h01;
        ((f162*)h)[2*o4+1] = h23;
    }
}

// ------------- pack KV biases in one kernel ---------------------------------
__global__ __launch_bounds__(256)
void pack_bias(const float* __restrict__ bk, const float* __restrict__ bv,
               float* __restrict__ bkv0, float* __restrict__ bkv1)
{
    int i = blockIdx.x * 256 + threadIdx.x;
    if (i >= DD) return;
    bkv0[i]      = bk[i];
    bkv0[DD + i] = bv[i];
    bkv1[i]      = bk[DD + i];
    bkv1[DD + i] = bv[DD + i];
}

// ========= single-f16 HMMA GEMM, KC=32, 2-stage cp.async ====================
#define A_STRIDE 80
#define B_STRIDE 272
#define KC 32
#define B_TILE 8704            // 32 * 272

template<int MT>
__device__ __forceinline__ void stage_load(
    uint32_t stg, const f16* __restrict__ A, const f16* __restrict__ B,
    int m0, int n0, int kc0, int M, int N, int K, int tid)
{
    constexpr int SA = MT * A_STRIDE;
    #pragma unroll
    for (int i = 0; i < MT / 64; i++) {
        int ca = tid + (i << 8);
        int r = ca >> 2, seg = ca & 3;
        int m = m0 + r;
        uint32_t dst = stg + (uint32_t)(r * A_STRIDE + seg * 16);
        int sz = (m < M) ? 16 : 0;
        size_t so = (size_t)m * K + kc0 + seg * 8;
        asm volatile("cp.async.cg.shared.global [%0], [%1], 16, %2;"
                     :: "r"(dst), "l"(A + so), "r"(sz));
    }
    #pragma unroll
    for (int i = 0; i < 2; i++) {
        int cb = tid + (i << 8);
        int r = cb >> 4, seg = cb & 15;
        uint32_t dst = stg + (uint32_t)(SA + r * B_STRIDE + seg * 16);
        size_t so = (size_t)(kc0 + r) * N + n0 + seg * 8;
        asm volatile("cp.async.cg.shared.global [%0], [%1], 16;"
                     :: "r"(dst), "l"(B + so));
    }
    asm volatile("cp.async.commit_group;");
}

template<int MT>
__global__ void __launch_bounds__(256, (MT == 64) ? 4 : 3)
mma_gemm(const f16* __restrict__ A, const f16* __restrict__ B,
         float* __restrict__ C, int M, int N, int K,
         const float* __restrict__ bias, const float* __restrict__ res, int relu,
         f16* __restrict__ Ch, int trans)
{
    constexpr int SA  = MT * A_STRIDE;
    constexpr int TSTG = SA + B_TILE;
    constexpr int WM = (MT == 128) ? 4 : 2;
    constexpr int NP = (MT == 128) ? 4 : 2;

    extern __shared__ __align__(128) char smem[];
    const uint32_t sb = smem_u32(smem);
    const int tid = threadIdx.x;
    const int wid = tid >> 5, lane = tid & 31;
    const int m0 = blockIdx.y * MT, n0 = blockIdx.x * 128;
    const int mw = (wid % WM) * 32;
    const int nw = (wid / WM) * (NP * 16);

    float acc[2][NP * 2][4];
    #pragma unroll
    for (int i = 0; i < 2; i++)
        #pragma unroll
        for (int j = 0; j < NP * 2; j++)
            #pragma unroll
            for (int q = 0; q < 4; q++) acc[i][j][q] = 0.f;

    const int lsub = lane >> 3, lr = lane & 7;
    const uint32_t aOff = (uint32_t)((lr + (lsub & 1) * 8) * A_STRIDE + (lsub >> 1) * 16);
    const uint32_t bOff = (uint32_t)((lr + (lsub & 1) * 8) * B_STRIDE + (lsub >> 1) * 16);

    const int nc = K / KC;
    stage_load<MT>(sb, A, B, m0, n0, 0, M, N, K, tid);

    for (int c = 0; c < nc; c++) {
        if (c + 1 < nc) {
            stage_load<MT>(sb + ((c + 1) & 1) * TSTG, A, B,
                           m0, n0, (c + 1) * KC, M, N, K, tid);
            asm volatile("cp.async.wait_group 1;");
        } else {
            asm volatile("cp.async.wait_group 0;");
        }
        __syncthreads();

        const uint32_t st = sb + (c & 1) * TSTG;
        #pragma unroll
        for (int ks = 0; ks < KC; ks += 16) {
            uint32_t ah[2][4];
            #pragma unroll
            for (int mi = 0; mi < 2; mi++) {
                uint32_t off = aOff + (uint32_t)((mw + mi * 16) * A_STRIDE + ks * 2);
                ldm_x4(ah[mi], st + off);
            }
            #pragma unroll
            for (int np = 0; np < NP; np++) {
                uint32_t off = bOff + (uint32_t)(ks * B_STRIDE + (nw + np * 16) * 2);
                uint32_t bh[4];
                ldm_x4_t(bh, st + SA + off);
                #pragma unroll
                for (int mi = 0; mi < 2; mi++)
                    #pragma unroll
                    for (int g2 = 0; g2 < 2; g2++)
                        mma_f16(acc[mi][np * 2 + g2], ah[mi], bh + g2 * 2);
            }
        }
        __syncthreads();
    }

    // ---- epilogue
    const int qrow = lane >> 2, qcol = (lane & 3) * 2;
    #pragma unroll
    for (int mi = 0; mi < 2; mi++) {
        int r0 = m0 + mw + mi * 16 + qrow;
        #pragma unroll
        for (int ni = 0; ni < NP * 2; ni++) {
            int cidx = n0 + nw + ni * 8 + qcol;
            float* a = acc[mi][ni];
            #pragma unroll
            for (int hh = 0; hh < 2; hh++) {
                int r = r0 + hh * 8;
                if (r >= M) continue;
                int ro = trans ? ((r % SS) * BB + r / SS) : r;
                float x = a[hh * 2 + 0] + bias[cidx];
                float y = a[hh * 2 + 1] + bias[cidx + 1];
                if (relu) { x = fmaxf(x, 0.f); y = fmaxf(y, 0.f); }
                if (res) {
                    const float2 rv = *(const float2*)&res[(size_t)ro * N + cidx];
                    x += rv.x; y += rv.y;
                }
                if (C) {
                    float2 o; o.x = x; o.y = y;
                    *(float2*)&C[(size_t)ro * N + cidx] = o;
                }
                if (Ch) {
                    *(f162*)&Ch[(size_t)ro * N + cidx] =
                        __halves2half2(__float2half_rn(x), __float2half_rn(y));
                }
            }
        }
    }
}

#define STG128 (128 * A_STRIDE + B_TILE)
#define STG64  (64  * A_STRIDE + B_TILE)

// ====== fused flash attention: q-tile 64, 128 threads, 3 CTAs/SM ============
#define FA_STRIDE 144
#define FA_K 0
#define FA_V 18432
#define FA_MASK 36864
#define FA_SMEM (FA_MASK + 512)

__global__ void __launch_bounds__(128, 3)
flash_attn(const f16* __restrict__ Q, const f16* __restrict__ K,
           const f16* __restrict__ V, const int* __restrict__ mask,
           f16* __restrict__ O,
           int Lq, int Lk, int qB, int qS, int oB, int kvld, float scale)
{
    extern __shared__ __align__(128) char smem[];
    const uint32_t sb = smem_u32(smem);
    const float* sbias = (const float*)(smem + FA_MASK);
    const int tid = threadIdx.x, wid = tid >> 5, lane = tid & 31;
    const int z = blockIdx.x, b = z / HH, h = z % HH;
    const int qb0 = blockIdx.y * 64;
    const int qt = lane >> 2, qc = (lane & 3) * 2;
    const int r0 = qb0 + wid * 16 + qt, r1 = r0 + 8;
    const int colh = h * DK;

    uint32_t qf[4][4];
    #pragma unroll
    for (int ks = 0; ks < 4; ks++) {
        #pragma unroll
        for (int p = 0; p < 4; p++) {
            int rr = (p & 1) ? r1 : r0;
            int kk = ks * 16 + qc + ((p >> 1) ? 8 : 0);
            if (rr < Lq) {
                size_t off = (size_t)(b * qB + rr * qS) * DD + colh + kk;
                qf[ks][p] = *(const uint32_t*)(Q + off);
            } else qf[ks][p] = 0u;
        }
    }

    float m0 = -1e30f, m1 = -1e30f, l0 = 0.f, l1 = 0.f;
    float oacc[8][4];
    #pragma unroll
    for (int j = 0; j < 8; j++)
        #pragma unroll
        for (int q = 0; q < 4; q++) oacc[j][q] = 0.f;

    const uint32_t ldOffK = (uint32_t)(((lane & 7) + ((lane >> 3) & 1) * 8) * FA_STRIDE
                                       + ((lane >> 4) * 8) * 2);

    const int nch = Lk / 128;
    for (int ch = 0; ch < nch; ch++) {
        const int k0g = ch * 128;
        #pragma unroll
        for (int i = 0; i < 8; i++) {
            int idx = tid + (i << 7);
            int r = idx >> 3, seg = idx & 7;
            size_t src = (size_t)(b * Lk + k0g + r) * kvld + colh + seg * 8;
            uint32_t dst = sb + (uint32_t)(r * FA_STRIDE + seg * 16);
            asm volatile("cp.async.cg.shared.global [%0], [%1], 16;" :: "r"(dst + FA_K), "l"(K + src));
            asm volatile("cp.async.cg.shared.global [%0], [%1], 16;" :: "r"(dst + FA_V), "l"(V + src));
        }
        asm volatile("cp.async.commit_group;");
        ((float*)(smem + FA_MASK))[tid] = mask[b * Lk + k0g + tid] ? 0.f : -1e9f;
        asm volatile("cp.async.wait_group 0;");
        __syncthreads();

        float sacc[16][4];
        #pragma unroll
        for (int j = 0; j < 16; j++)
            #pragma unroll
            for (int q = 0; q < 4; q++) sacc[j][q] = 0.f;

        #pragma unroll
        for (int ks = 0; ks < 4; ks++) {
            #pragma unroll
            for (int nt = 0; nt < 8; nt++) {
                uint32_t off = ldOffK + (uint32_t)(nt * 16 * FA_STRIDE + ks * 32);
                uint32_t kh4[4];
                ldm_x4(kh4, sb + FA_K + off);
                #pragma unroll
                for (int sub = 0; sub < 2; sub++)
                    mma_f16_b(sacc[nt * 2 + sub], qf[ks], kh4[sub], kh4[sub + 2]);
            }
        }

        float cm0 = -1e30f, cm1 = -1e30f;
        #pragma unroll
        for (int j = 0; j < 16; j++) {
            int kb = j * 8 + qc;
            float b0v = sbias[kb], b1v = sbias[kb + 1];
            sacc[j][0] = sacc[j][0] * scale + b0v;
            sacc[j][1] = sacc[j][1] * scale + b1v;
            sacc[j][2] = sacc[j][2] * scale + b0v;
            sacc[j][3] = sacc[j][3] * scale + b1v;
            cm0 = fmaxf(cm0, fmaxf(sacc[j][0], sacc[j][1]));
            cm1 = fmaxf(cm1, fmaxf(sacc[j][2], sacc[j][3]));
        }
        cm0 = fmaxf(cm0, __shfl_xor_sync(0xFFFFFFFFu, cm0, 1));
        cm0 = fmaxf(cm0, __shfl_xor_sync(0xFFFFFFFFu, cm0, 2));
        cm1 = fmaxf(cm1, __shfl_xor_sync(0xFFFFFFFFu, cm1, 1));
        cm1 = fmaxf(cm1, __shfl_xor_sync(0xFFFFFFFFu, cm1, 2));
        float nm0 = fmaxf(m0, cm0), nm1 = fmaxf(m1, cm1);
        float al0 = __expf(m0 - nm0), al1 = __expf(m1 - nm1);
        m0 = nm0; m1 = nm1;

        float ps0 = 0.f, ps1 = 0.f;
        #pragma unroll
        for (int j = 0; j < 16; j++) {
            float p0 = __expf(sacc[j][0] - nm0), p1 = __expf(sacc[j][1] - nm0);
            float p2 = __expf(sacc[j][2] - nm1), p3 = __expf(sacc[j][3] - nm1);
            ps0 += p0 + p1; ps1 += p2 + p3;
            sacc[j][0] = p0; sacc[j][1] = p1; sacc[j][2] = p2; sacc[j][3] = p3;
        }
        ps0 += __shfl_xor_sync(0xFFFFFFFFu, ps0, 1);
        ps0 += __shfl_xor_sync(0xFFFFFFFFu, ps0, 2);
        ps1 += __shfl_xor_sync(0xFFFFFFFFu, ps1, 1);
        ps1 += __shfl_xor_sync(0xFFFFFFFFu, ps1, 2);
        l0 = l0 * al0 + ps0; l1 = l1 * al1 + ps1;
        #pragma unroll
        for (int j = 0; j < 8; j++) {
            oacc[j][0] *= al0; oacc[j][1] *= al0;
            oacc[j][2] *= al1; oacc[j][3] *= al1;
        }

        #pragma unroll
        for (int kk = 0; kk < 8; kk++) {
            uint32_t ahp[4], alp[4];
            #pragma unroll
            for (int jj = 0; jj < 2; jj++) {
                const float* sp = sacc[2 * kk + jj];
                f162 h01, l01, h23, l23;
                split2h(sp[0], sp[1], h01, l01);
                split2h(sp[2], sp[3], h23, l23);
                ahp[jj * 2 + 0] = *(uint32_t*)&h01; ahp[jj * 2 + 1] = *(uint32_t*)&h23;
                alp[jj * 2 + 0] = *(uint32_t*)&l01; alp[jj * 2 + 1] = *(uint32_t*)&l23;
            }
            #pragma unroll
            for (int dt = 0; dt < 4; dt++) {
                uint32_t off = ldOffK + (uint32_t)(kk * 16 * FA_STRIDE + dt * 32);
                uint32_t vh4[4];
                ldm_x4_t(vh4, sb + FA_V + off);
                #pragma unroll
                for (int sub = 0; sub < 2; sub++)
                    mma_f16_b(oacc[dt * 2 + sub], ahp, vh4[sub*2], vh4[sub*2+1]);
                #pragma unroll
                for (int sub = 0; sub < 2; sub++)
                    mma_f16_b(oacc[dt * 2 + sub], alp, vh4[sub*2], vh4[sub*2+1]);
            }
        }
        __syncthreads();
    }

    float inv0 = 1.f / l0, inv1 = 1.f / l1;
    #pragma unroll
    for (int j = 0; j < 8; j++) {
        int col = colh + j * 8 + qc;
        if (r0 < Lq) {
            size_t off = (size_t)(b * oB + r0) * DD + col;
            *(f162*)(O + off) = __halves2half2(__float2half_rn(oacc[j][0] * inv0),
                                               __float2half_rn(oacc[j][1] * inv0));
        }
        if (r1 < Lq) {
            size_t off = (size_t)(b * oB + r1) * DD + col;
            *(f162*)(O + off) = __halves2half2(__float2half_rn(oacc[j][2] * inv1),
                                               __float2half_rn(oacc[j][3] * inv1));
        }
    }
}

// ------- LayerNorm: warp per row, single pass, register resident ------------
__global__ __launch_bounds__(256)
void ln_warp(const float* __restrict__ x, float* __restrict__ y,
             f16* __restrict__ yh,
             const float* __restrict__ g, const float* __restrict__ be)
{
    const int lane = threadIdx.x & 31;
    const size_t row = (size_t)(blockIdx.x * 8) + (threadIdx.x >> 5);
    const float* xr = x + row * DD;

    float4 v[6];
    float s = 0.f, s2 = 0.f;
    #pragma unroll
    for (int i = 0; i < 6; i++) {
        v[i] = *(const float4*)&xr[i * 128 + lane * 4];
        s  += v[i].x + v[i].y + v[i].z + v[i].w;
        s2 += v[i].x * v[i].x + v[i].y * v[i].y + v[i].z * v[i].z + v[i].w * v[i].w;
    }
    #pragma unroll
    for (int o = 16; o > 0; o >>= 1) {
        s  += __shfl_xor_sync(0xFFFFFFFFu, s, o);
        s2 += __shfl_xor_sync(0xFFFFFFFFu, s2, o);
    }
    const float mean = s * (1.f / DD);
    const float var  = s2 * (1.f / DD) - mean * mean;
    const float rstd = rsqrtf(var + 1e-5f);

    #pragma unroll
    for (int i = 0; i < 6; i++) {
        int col = i * 128 + lane * 4;
        float4 gv = *(const float4*)&g[col];
        float4 bv = *(const float4*)&be[col];
        float4 o;
        o.x = (v[i].x - mean) * rstd * gv.x + bv.x;
        o.y = (v[i].y - mean) * rstd * gv.y + bv.y;
        o.z = (v[i].z - mean) * rstd * gv.z + bv.z;
        o.w = (v[i].w - mean) * rstd * gv.w + bv.w;
        if (y) *(float4*)&y[row * DD + col] = o;
        if (yh) {
            *(f162*)&yh[row * DD + col] =
                __halves2half2(__float2half_rn(o.x), __float2half_rn(o.y));
            *(f162*)&yh[row * DD + col + 2] =
                __halves2half2(__float2half_rn(o.z), __float2half_rn(o.w));
        }
    }
}

// ---------------- host-side helpers ----------------------------------------
template<typename T>
static T* sym(const void* s) { void* p = nullptr; cudaGetSymbolAddress(&p, s); return (T*)p; }

static void run_lin_s(cudaStream_t st, const f16* A, const f16* W,
                      float* C, int M, int N, int K,
                      const float* bias, const float* res, int relu,
                      f16* Ch = nullptr, int trans = 0)
{
    int ctas128 = (N / 128) * ((M + 127) / 128);
    if (M <= 4096 && ctas128 < 232) {
        dim3 grid(N / 128, (M + 63) / 64);
        mma_gemm<64><<<grid, 256, 2 * STG64, st>>>(A, W, C, M, N, K, bias, res, relu, Ch, trans);
    } else {
        dim3 grid(N / 128, (M + 127) / 128);
        mma_gemm<128><<<grid, 256, 2 * STG128, st>>>(A, W, C, M, N, K, bias, res, relu, Ch, trans);
    }
}

extern "C" void kernel_launch(void* const* d_in, const int* in_sizes, int n_in,
                              void* d_out, int out_size)
{
    static bool s_init = false;
    static cudaStream_t s1, s2;
    static cudaEvent_t eS, e0, e1, e2, eW;
    if (!s_init) {
        cudaFuncSetAttribute(mma_gemm<128>, cudaFuncAttributeMaxDynamicSharedMemorySize, 2 * STG128);
        cudaFuncSetAttribute(mma_gemm<64>,  cudaFuncAttributeMaxDynamicSharedMemorySize, 2 * STG64);
        cudaFuncSetAttribute(flash_attn, cudaFuncAttributeMaxDynamicSharedMemorySize, FA_SMEM);
        cudaStreamCreateWithFlags(&s1, cudaStreamNonBlocking);
        cudaStreamCreateWithFlags(&s2, cudaStreamNonBlocking);
        cudaEventCreateWithFlags(&eS, cudaEventDisableTiming);
        cudaEventCreateWithFlags(&e0, cudaEventDisableTiming);
        cudaEventCreateWithFlags(&e1, cudaEventDisableTiming);
        cudaEventCreateWithFlags(&e2, cudaEventDisableTiming);
        cudaEventCreateWithFlags(&eW, cudaEventDisableTiming);
        s_init = true;
    }

    const float* cur_raw  = (const float*)d_in[0];
    const float* ctx_raw  = (const float*)d_in[1];
    const float* pre_raw  = (const float*)d_in[2];
    const int*   ctx_mask = (const int*)d_in[3];
    const int*   utt_mask = (const int*)d_in[4];
    const float* norm_W   = (const float*)d_in[5];
    const float* norm_b   = (const float*)d_in[6];
    const float* norm_g   = (const float*)d_in[7];
    const float* norm_be  = (const float*)d_in[8];
    const float* Wq = (const float*)d_in[9];
    const float* bq = (const float*)d_in[10];
    const float* Wk = (const float*)d_in[11];
    const float* bk = (const float*)d_in[12];
    const float* Wv = (const float*)d_in[13];
    const float* bv = (const float*)d_in[14];
    const float* Wo = (const float*)d_in[15];
    const float* bo = (const float*)d_in[16];
    const float* ln_g = (const float*)d_in[17];
    const float* ln_b = (const float*)d_in[18];
    const float* W1 = (const float*)d_in[19];
    const float* b1 = (const float*)d_in[20];
    const float* W2 = (const float*)d_in[21];
    const float* b2 = (const float*)d_in[22];

    float* out  = (float*)d_out;
    float* cur_out   = out;
    float* slots_out = out + (long long)BB * LU * DD;

    float* fea_cur   = sym<float>(g_fea_cur);
    float* fea_ctx   = sym<float>(g_fea_ctx);
    float* fea_slots = sym<float>(g_fea_slots);
    float* cur_attn  = sym<float>(g_cur_attn);
    float* va = sym<float>(g_va);
    float* bkv0 = sym<float>(g_bkv0);
    float* bkv1 = sym<float>(g_bkv1);

    f16 *wn = sym<f16>(g_wn);
    f16 *wq = sym<f16>(g_wq);
    f16 *wkv0 = sym<f16>(g_wkv0);
    f16 *wkv1 = sym<f16>(g_wkv1);
    f16 *wo = sym<f16>(g_wo);
    f16 *w1 = sym<f16>(g_w1);
    f16 *w2 = sym<f16>(g_w2);
    f16 *xcur = sym<f16>(g_xcur);
    f16 *xctx = sym<f16>(g_xctx);
    f16 *xpre = sym<f16>(g_xpre);
    f16 *fc = sym<f16>(g_fc);
    f16 *fx = sym<f16>(g_fx);
    f16 *fs = sym<f16>(g_fs);
    f16 *lnb = sym<f16>(g_lnb);
    f16 *ffh = sym<f16>(g_ffh);
    f16 *a0 = sym<f16>(g_a0);
    f16 *a1 = sym<f16>(g_a1);
    f16 *co = sym<f16>(g_co);
    f16 *q0 = sym<f16>(g_q0);
    f16 *kv0 = sym<f16>(g_kv0);
    f16 *q1 = sym<f16>(g_q1);
    f16 *kv1 = sym<f16>(g_kv1);

    const int DxD = DD * DD;
    const int N2 = 2 * DD;

    // ---- fork point: everything below hangs off the main stream
    pack_bias<<<(DD + 255) / 256, 256>>>(bk, bv, bkv0, bkv1);
    cudaEventRecord(eS, 0);

    // ---- s1 joins capture, then runs conv group B (weights) concurrently
    cudaStreamWaitEvent(s1, eS, 0);
    {
        ConvArgs ca;
        const float* xs[8] = { Wq, Wo, W1, W2, Wk, Wv, Wk + DxD, Wv + DxD };
        f16* hs[8] = { wq, wo, w1, w2, wkv0, wkv0, wkv1, wkv1 };
        int ns[8] = { 2*DxD/4, 2*DxD/4, 2*DD*DFF/4, 2*DFF*DD/4,
                      DxD/4, DxD/4, DxD/4, DxD/4 };
        int ld4[8] = { 192, 192, 192, 192, 384, 384, 384, 384 };
        int co4[8] = { 0, 0, 0, 0, 0, 192, 0, 192 };
        for (int i = 0; i < 8; i++) {
            ca.x[i]=xs[i]; ca.h[i]=hs[i]; ca.n4[i]=ns[i];
            ca.ldo4[i]=ld4[i]; ca.coff4[i]=co4[i];
        }
        conv_multi<<<dim3(96, 8), 256, 0, s1>>>(ca);
    }
    cudaEventRecord(eW, s1);

    // ---- conv group A (inputs + norm weights) on main
    {
        ConvArgs ca;
        const float* xs[4] = { norm_W, cur_raw, ctx_raw, pre_raw };
        f16* hs[4] = { wn, xcur, xctx, xpre };
        int ns[4] = { 3*DxD/4, BB*LU*DD/4, BB*LC*DD/4, SS*BB*DD/4 };
        for (int i = 0; i < 4; i++) {
            ca.x[i]=xs[i]; ca.h[i]=hs[i]; ca.n4[i]=ns[i];
            ca.ldo4[i]=192; ca.coff4[i]=0;
        }
        conv_multi<<<dim3(160, 4), 256>>>(ca);
    }
    cudaEventRecord(e0, 0);

    // ---- s1: cur chain (needs conv A for xcur/wn; wq from its own conv B)
    cudaStreamWaitEvent(s1, e0, 0);
    run_lin_s(s1, xcur, wn, fea_cur, BB * LU, DD, DD, norm_b, nullptr, 0);
    ln_warp<<<BB * LU / 8, 256, 0, s1>>>(fea_cur, fea_cur, fc, norm_g, norm_be);
    run_lin_s(s1, fc, wq, nullptr, BB * LU, DD, DD, bq, nullptr, 0, q0);
    cudaEventRecord(e1, s1);

    // ---- s2: slots chain (needs conv A + wq from conv B)
    cudaStreamWaitEvent(s2, e0, 0);
    cudaStreamWaitEvent(s2, eW, 0);
    run_lin_s(s2, xpre, wn + 2 * DxD, fea_slots, SS * BB, DD, DD,
              norm_b + 2 * DD, nullptr, 0);
    ln_warp<<<SS * BB / 8, 256, 0, s2>>>(fea_slots, fea_slots, fs,
                                         norm_g + 2 * DD, norm_be + 2 * DD);
    run_lin_s(s2, fs, wq + DxD, nullptr, SS * BB, DD, DD, bq + DD, nullptr, 0, q1);
    cudaEventRecord(e2, s2);

    // ---- main: ctx chain (norm -> LN -> fused K0|V0)
    run_lin_s(0, xctx, wn + DxD, fea_ctx, BB * LC, DD, DD, norm_b + DD, nullptr, 0);
    ln_warp<<<BB * LC / 8, 256>>>(fea_ctx, nullptr, fx, norm_g + DD, norm_be + DD);
    cudaStreamWaitEvent(0, eW, 0);
    run_lin_s(0, fx, wkv0, nullptr, BB * LC, N2, DD, bkv0, nullptr, 0, kv0);

    cudaStreamWaitEvent(0, e1, 0);

    // ---- stage B (main)
    flash_attn<<<dim3(BB * HH, 2), 128, FA_SMEM>>>(q0, kv0, kv0 + DD, ctx_mask, a0,
                                                   LU, LC, LU, 1, LU, N2, 0.125f);
    run_lin_s(0, a0, wo, cur_attn, BB * LU, DD, DD, bo, fea_cur, 0);
    ln_warp<<<BB * LU / 8, 256>>>(cur_attn, nullptr, lnb, ln_g, ln_b);
    run_lin_s(0, lnb, w1, nullptr, BB * LU, DFF, DD, b1, nullptr, 1, ffh);
    run_lin_s(0, ffh, w2, cur_out, BB * LU, DD, DFF, b2, cur_attn, 0, co);

    // ---- stage C (main): fused K1|V1
    run_lin_s(0, co, wkv1, nullptr, BB * LU, N2, DD, bkv1, nullptr, 0, kv1);

    cudaStreamWaitEvent(0, e2, 0);

    flash_attn<<<dim3(BB * HH, 1), 128, FA_SMEM>>>(q1, kv1, kv1 + DD, utt_mask, a1,
                                                   SS, LU, 1, BB, SS, N2, 0.125f);

    // Wo-proj with fused transpose-residual: va[S,B,D] = (a1@Wo + bo) + fea_slots
    run_lin_s(0, a1, wo + DxD, va, BB * SS, DD, DD, bo + DD, fea_slots, 0, nullptr, 1);

    ln_warp<<<SS * BB / 8, 256>>>(va, nullptr, lnb, ln_g + DD, ln_b + DD);
    run_lin_s(0, lnb, w1 + DD * DFF, nullptr, SS * BB, DFF, DD, b1 + DFF, nullptr, 1, ffh);
    run_lin_s(0, ffh, w2 + DFF * DD, slots_out, SS * BB, DD, DFF, b2 + DD, va, 0);
}